// round 1
// baseline (speedup 1.0000x reference)
#include <cuda_runtime.h>
#include <cuda_bf16.h>
#include <cstdint>

#define N_NODES 100000
#define N_EDGES 3200000
#define HID 64
#define OUT_D 64

// ---------------- scratch (static device memory; no runtime allocs) ----------------
__device__ float g_h[N_NODES * 64];     // h (layer1), then h2 (layer2)
__device__ float g_acc[N_NODES * 64];   // unnormalized aggregation accumulator (both layers)
__device__ float g_act[N_NODES * 64];   // act1 = relu(out1)
__device__ float g_als1[N_NODES * 2];   // layer1 al_src per head
__device__ float g_ald1[N_NODES * 2];   // layer1 al_dst per head
__device__ float g_als2[N_NODES];       // layer2 al_src
__device__ float g_ald2[N_NODES];       // layer2 al_dst
__device__ float g_s1[N_NODES * 2];     // layer1 softmax denominators
__device__ float g_s2[N_NODES];         // layer2 softmax denominators
__device__ unsigned g_maxkey[8];        // 0:s1h0 1:s1h1 2:d1h0 3:d1h1 4:s2 5:d2

// ---------------- helpers ----------------
__device__ __forceinline__ float leaky(float x) { return x > 0.f ? x : 0.2f * x; }

// monotonic float -> unsigned key for atomicMax
__device__ __forceinline__ unsigned fkey(float f) {
    unsigned u = __float_as_uint(f);
    return (u & 0x80000000u) ? ~u : (u | 0x80000000u);
}
__device__ __forceinline__ float funkey(unsigned u) {
    return __uint_as_float((u & 0x80000000u) ? (u ^ 0x80000000u) : ~u);
}

__device__ __forceinline__ void red_add_v4(float* p, float a, float b, float c, float d) {
    asm volatile("red.global.add.v4.f32 [%0], {%1,%2,%3,%4};"
                 :: "l"(p), "f"(a), "f"(b), "f"(c), "f"(d) : "memory");
}

// ---------------- zero kernels ----------------
__global__ void zero1_kernel() {
    int i = blockIdx.x * blockDim.x + threadIdx.x;
    if (i < N_NODES * 64) g_acc[i] = 0.f;
    if (i < N_NODES * 2) g_s1[i] = 0.f;
    if (i < 4) g_maxkey[i] = 0u;
}
__global__ void zero2_kernel() {
    int i = blockIdx.x * blockDim.x + threadIdx.x;
    if (i < N_NODES * 64) g_acc[i] = 0.f;
    if (i < N_NODES) g_s2[i] = 0.f;
    if (i < 2) g_maxkey[4 + i] = 0u;
}

// ---------------- node kernel layer 1: xin @ W1, al scores, global max ----------------
__global__ void node1_kernel(const float* __restrict__ x, const int* __restrict__ tids,
                             const float* __restrict__ temb, const float* __restrict__ W1,
                             const float* __restrict__ a_s, const float* __restrict__ a_d) {
    __shared__ float Ws[21 * 64];
    __shared__ float xin[4][21];
    __shared__ float redS[8], redD[8];
    int t = threadIdx.x;
    for (int i = t; i < 21 * 64; i += 256) Ws[i] = W1[i];
    int ln = t >> 6, f = t & 63;
    int node = blockIdx.x * 4 + ln;
    if (node < N_NODES && f < 21) {
        if (f < 5) xin[ln][f] = x[node * 5 + f];
        else {
            int ty = tids[node];
            xin[ln][f] = temb[ty * 16 + (f - 5)];
        }
    }
    __syncthreads();
    int w = t >> 5;
    if (node < N_NODES) {
        float acc = 0.f;
#pragma unroll
        for (int j = 0; j < 21; j++) acc += xin[ln][j] * Ws[j * 64 + f];
        g_h[node * 64 + f] = acc;
        int head = f >> 5, c = f & 31;
        float ps = acc * a_s[head * 32 + c];
        float pd = acc * a_d[head * 32 + c];
#pragma unroll
        for (int o = 16; o; o >>= 1) {
            ps += __shfl_down_sync(0xFFFFFFFFu, ps, o);
            pd += __shfl_down_sync(0xFFFFFFFFu, pd, o);
        }
        if (c == 0) {
            g_als1[node * 2 + head] = ps;
            g_ald1[node * 2 + head] = pd;
            redS[w] = ps; redD[w] = pd;
        }
    } else if ((t & 31) == 0) {
        redS[w] = -1e30f; redD[w] = -1e30f;
    }
    __syncthreads();
    if (t < 4) { // t: 0=(s,h0) 1=(s,h1) 2=(d,h0) 3=(d,h1); head-h warps are w%2==h
        float* arr = (t < 2) ? redS : redD;
        int h = t & 1;
        float m = fmaxf(fmaxf(arr[h], arr[2 + h]), fmaxf(arr[4 + h], arr[6 + h]));
        atomicMax(&g_maxkey[t], fkey(m));
    }
}

// ---------------- edge kernel layer 1 ----------------
__global__ void edge1_kernel(const int* __restrict__ ei) {
    int gw = (blockIdx.x * blockDim.x + threadIdx.x) >> 5;
    int lane = threadIdx.x & 31;
    int e = gw * 2 + (lane >> 4);
    int sub = lane & 15;
    float M0 = leaky(funkey(g_maxkey[0]) + funkey(g_maxkey[2]));
    float M1 = leaky(funkey(g_maxkey[1]) + funkey(g_maxkey[3]));
    if (e >= N_EDGES) return;
    int src = __ldg(&ei[e]);
    int dst = __ldg(&ei[N_EDGES + e]);
    float2 as = *(const float2*)&g_als1[src * 2];
    float2 ad = *(const float2*)&g_ald1[dst * 2];
    float w0 = __expf(leaky(as.x + ad.x) - M0);
    float w1 = __expf(leaky(as.y + ad.y) - M1);
    float4 hv = *(const float4*)&g_h[src * 64 + sub * 4];
    float w = (sub < 8) ? w0 : w1;
    red_add_v4(&g_acc[dst * 64 + sub * 4], w * hv.x, w * hv.y, w * hv.z, w * hv.w);
    if (sub == 0) {
        atomicAdd(&g_s1[dst * 2], w0);
        atomicAdd(&g_s1[dst * 2 + 1], w1);
    }
}

// ---------------- finalize layer 1: self loop + normalize + bias + relu ----------------
__global__ void fin1_kernel(const float* __restrict__ b1) {
    int t = blockIdx.x * blockDim.x + threadIdx.x;
    if (t >= N_NODES * 64) return;
    int node = t >> 6, f = t & 63, head = f >> 5;
    float M = leaky(funkey(g_maxkey[head]) + funkey(g_maxkey[2 + head]));
    float al = g_als1[node * 2 + head] + g_ald1[node * 2 + head];
    float wself = __expf(leaky(al) - M);
    float denom = g_s1[node * 2 + head] + wself + 1e-16f;
    float v = (g_acc[t] + wself * g_h[t]) / denom + b1[f];
    g_act[t] = fmaxf(v, 0.f);
}

// ---------------- node kernel layer 2: act1 @ W2, al scores, global max ----------------
__global__ void node2_kernel(const float* __restrict__ W2, const float* __restrict__ a_s2,
                             const float* __restrict__ a_d2) {
    __shared__ float Ws[64 * 64];
    __shared__ float xin[4][64];
    __shared__ float redS[8], redD[8];
    __shared__ float asv[4], adv[4];
    int t = threadIdx.x;
    for (int i = t; i < 64 * 64; i += 256) Ws[i] = W2[i];
    int ln = t >> 6, f = t & 63;
    int node = blockIdx.x * 4 + ln;
    if (node < N_NODES) xin[ln][f] = g_act[node * 64 + f];
    __syncthreads();
    float ps = 0.f, pd = 0.f;
    if (node < N_NODES) {
        float acc = 0.f;
#pragma unroll
        for (int j = 0; j < 64; j++) acc += xin[ln][j] * Ws[j * 64 + f];
        g_h[node * 64 + f] = acc;
        ps = acc * a_s2[f];
        pd = acc * a_d2[f];
    }
#pragma unroll
    for (int o = 16; o; o >>= 1) {
        ps += __shfl_down_sync(0xFFFFFFFFu, ps, o);
        pd += __shfl_down_sync(0xFFFFFFFFu, pd, o);
    }
    int w = t >> 5;
    if ((t & 31) == 0) { redS[w] = ps; redD[w] = pd; }
    __syncthreads();
    if (t < 4) {
        int nd = blockIdx.x * 4 + t;
        if (nd < N_NODES) {
            float as = redS[2 * t] + redS[2 * t + 1];
            float ad = redD[2 * t] + redD[2 * t + 1];
            g_als2[nd] = as; g_ald2[nd] = ad;
            asv[t] = as; adv[t] = ad;
        } else { asv[t] = -1e30f; adv[t] = -1e30f; }
    }
    __syncthreads();
    if (t == 0) {
        float ms = fmaxf(fmaxf(asv[0], asv[1]), fmaxf(asv[2], asv[3]));
        float md = fmaxf(fmaxf(adv[0], adv[1]), fmaxf(adv[2], adv[3]));
        atomicMax(&g_maxkey[4], fkey(ms));
        atomicMax(&g_maxkey[5], fkey(md));
    }
}

// ---------------- edge kernel layer 2 ----------------
__global__ void edge2_kernel(const int* __restrict__ ei) {
    int gw = (blockIdx.x * blockDim.x + threadIdx.x) >> 5;
    int lane = threadIdx.x & 31;
    int e = gw * 2 + (lane >> 4);
    int sub = lane & 15;
    float M = leaky(funkey(g_maxkey[4]) + funkey(g_maxkey[5]));
    if (e >= N_EDGES) return;
    int src = __ldg(&ei[e]);
    int dst = __ldg(&ei[N_EDGES + e]);
    float as = __ldg(&g_als2[src]);
    float ad = __ldg(&g_ald2[dst]);
    float w = __expf(leaky(as + ad) - M);
    float4 hv = *(const float4*)&g_h[src * 64 + sub * 4];
    red_add_v4(&g_acc[dst * 64 + sub * 4], w * hv.x, w * hv.y, w * hv.z, w * hv.w);
    if (sub == 0) atomicAdd(&g_s2[dst], w);
}

// ---------------- finalize layer 2: self loop + normalize + bias + layernorm ----------------
__global__ void fin2_kernel(const float* __restrict__ b2, const float* __restrict__ gamma,
                            const float* __restrict__ beta, float* __restrict__ out) {
    __shared__ float rs[8], rq[8];
    int t = threadIdx.x;
    int ln = t >> 6, f = t & 63;
    int node = blockIdx.x * 4 + ln;
    float v = 0.f;
    if (node < N_NODES) {
        float M = leaky(funkey(g_maxkey[4]) + funkey(g_maxkey[5]));
        float al = g_als2[node] + g_ald2[node];
        float ws = __expf(leaky(al) - M);
        float denom = g_s2[node] + ws + 1e-16f;
        v = (g_acc[node * 64 + f] + ws * g_h[node * 64 + f]) / denom + b2[f];
    }
    float s = v, q = v * v;
#pragma unroll
    for (int o = 16; o; o >>= 1) {
        s += __shfl_down_sync(0xFFFFFFFFu, s, o);
        q += __shfl_down_sync(0xFFFFFFFFu, q, o);
    }
    int w = t >> 5;
    if ((t & 31) == 0) { rs[w] = s; rq[w] = q; }
    __syncthreads();
    if (node < N_NODES) {
        int w0 = ln * 2;
        float sum = rs[w0] + rs[w0 + 1];
        float sq = rq[w0] + rq[w0 + 1];
        float mu = sum * (1.f / 64.f);
        float var = sq * (1.f / 64.f) - mu * mu;
        float inv = rsqrtf(var + 1e-5f);
        out[node * 64 + f] = (v - mu) * inv * gamma[f] + beta[f];
    }
}

// ---------------- launch ----------------
extern "C" void kernel_launch(void* const* d_in, const int* in_sizes, int n_in,
                              void* d_out, int out_size) {
    // Detect input ordering: setup_inputs dict order vs reference signature order.
    const float *x, *temb, *W1, *as1, *ad1, *b1, *W2, *as2, *ad2, *b2, *gamma, *beta;
    const int *ei, *tids;
    if (in_sizes[1] == 2 * N_EDGES) {
        // dict order: x, edge_index, type_ids, type_emb, W1, a_src1, a_dst1, b1, W2, a_src2, a_dst2, b2, gamma, beta
        x    = (const float*)d_in[0];
        ei   = (const int*)d_in[1];
        tids = (const int*)d_in[2];
        temb = (const float*)d_in[3];
        W1   = (const float*)d_in[4];
        as1  = (const float*)d_in[5];
        ad1  = (const float*)d_in[6];
        b1   = (const float*)d_in[7];
        W2   = (const float*)d_in[8];
        as2  = (const float*)d_in[9];
        ad2  = (const float*)d_in[10];
        b2   = (const float*)d_in[11];
        gamma= (const float*)d_in[12];
        beta = (const float*)d_in[13];
    } else {
        // reference signature order
        x    = (const float*)d_in[0];
        temb = (const float*)d_in[1];
        W1   = (const float*)d_in[2];
        as1  = (const float*)d_in[3];
        ad1  = (const float*)d_in[4];
        b1   = (const float*)d_in[5];
        W2   = (const float*)d_in[6];
        as2  = (const float*)d_in[7];
        ad2  = (const float*)d_in[8];
        b2   = (const float*)d_in[9];
        gamma= (const float*)d_in[10];
        beta = (const float*)d_in[11];
        ei   = (const int*)d_in[12];
        tids = (const int*)d_in[13];
    }
    float* out = (float*)d_out;

    const int zeroBlocks = (N_NODES * 64 + 255) / 256;
    const int nodeBlocks = (N_NODES + 3) / 4;
    const int edgeBlocks = (N_EDGES + 15) / 16;  // 256 thr = 8 warps = 16 edges / block
    const int finBlocks  = (N_NODES * 64 + 255) / 256;

    zero1_kernel<<<zeroBlocks, 256>>>();
    node1_kernel<<<nodeBlocks, 256>>>(x, tids, temb, W1, as1, ad1);
    edge1_kernel<<<edgeBlocks, 256>>>(ei);
    fin1_kernel<<<finBlocks, 256>>>(b1);
    zero2_kernel<<<zeroBlocks, 256>>>();
    node2_kernel<<<nodeBlocks, 256>>>(W2, as2, ad2);
    edge2_kernel<<<edgeBlocks, 256>>>(ei);
    fin2_kernel<<<nodeBlocks, 256>>>(b2, gamma, beta, out);
}

// round 3
// speedup vs baseline: 1.5288x; 1.5288x over previous
#include <cuda_runtime.h>
#include <cuda_bf16.h>
#include <cstdint>

#define N_NODES 100000
#define N_EDGES 3200000
#define SCHUNK 1024
#define NCHUNK ((N_NODES + SCHUNK - 1) / SCHUNK)

// ---------------- scratch (static device memory) ----------------
__device__ float g_h[N_NODES * 64];     // h (layer1), then h2 (layer2)
__device__ float g_act[N_NODES * 64];   // relu(out1)
__device__ float g_als1[N_NODES * 2];
__device__ float g_ald1[N_NODES * 2];
__device__ float g_als2[N_NODES];
__device__ float g_ald2[N_NODES];
__device__ unsigned g_maxkey[8];        // 0:s1h0 1:s1h1 2:d1h0 3:d1h1 4:s2 5:d2
__device__ int g_deg[N_NODES];
__device__ int g_rowoff[N_NODES + 1];
__device__ int g_cursor[N_NODES];
__device__ int g_csr[N_EDGES];          // src ids grouped by dst
__device__ int g_part[NCHUNK];

// ---------------- helpers ----------------
__device__ __forceinline__ float leaky(float x) { return x > 0.f ? x : 0.2f * x; }
__device__ __forceinline__ unsigned fkey(float f) {
    unsigned u = __float_as_uint(f);
    return (u & 0x80000000u) ? ~u : (u | 0x80000000u);
}
__device__ __forceinline__ float funkey(unsigned u) {
    return __uint_as_float((u & 0x80000000u) ? (u ^ 0x80000000u) : ~u);
}

// ---------------- CSR build ----------------
__global__ void zero_kernel() {
    int i = blockIdx.x * blockDim.x + threadIdx.x;
    if (i < N_NODES) g_deg[i] = 0;
    if (i < 8) g_maxkey[i] = 0u;
}
__global__ void hist_kernel(const int* __restrict__ ei) {
    int i = blockIdx.x * blockDim.x + threadIdx.x;
    if (i < N_EDGES) atomicAdd(&g_deg[__ldg(&ei[N_EDGES + i])], 1);
}
__global__ void scan1_kernel() {
    __shared__ int wsum[32];
    int t = threadIdx.x;
    int i = blockIdx.x * SCHUNK + t;
    int v = (i < N_NODES) ? g_deg[i] : 0;
    int x = v;
#pragma unroll
    for (int o = 1; o < 32; o <<= 1) {
        int y = __shfl_up_sync(0xFFFFFFFFu, x, o);
        if ((t & 31) >= o) x += y;
    }
    if ((t & 31) == 31) wsum[t >> 5] = x;
    __syncthreads();
    if (t < 32) {
        int y = wsum[t];
#pragma unroll
        for (int o = 1; o < 32; o <<= 1) {
            int z = __shfl_up_sync(0xFFFFFFFFu, y, o);
            if (t >= o) y += z;
        }
        wsum[t] = y;
    }
    __syncthreads();
    int base = (t >= 32) ? wsum[(t >> 5) - 1] : 0;
    int incl = x + base;
    if (i < N_NODES) g_rowoff[i] = incl - v;   // chunk-local exclusive
    if (t == SCHUNK - 1) g_part[blockIdx.x] = incl;
}
__global__ void scan2_kernel() {
    __shared__ int s[NCHUNK];
    int t = threadIdx.x;
    if (t < NCHUNK) s[t] = g_part[t];
    __syncthreads();
    if (t == 0) {
        int run = 0;
        for (int b = 0; b < NCHUNK; b++) { int v = s[b]; s[b] = run; run += v; }
        g_rowoff[N_NODES] = run;
    }
    __syncthreads();
    if (t < NCHUNK) g_part[t] = s[t];
}
__global__ void scan3_kernel() {
    int i = blockIdx.x * blockDim.x + threadIdx.x;
    if (i < N_NODES) {
        int v = g_rowoff[i] + g_part[i >> 10];
        g_rowoff[i] = v;
        g_cursor[i] = v;
    }
}
__global__ void scatter_kernel(const int* __restrict__ ei) {
    int i = blockIdx.x * blockDim.x + threadIdx.x;
    if (i < N_EDGES) {
        int dst = __ldg(&ei[N_EDGES + i]);
        int pos = atomicAdd(&g_cursor[dst], 1);
        g_csr[pos] = __ldg(&ei[i]);
    }
}

// ---------------- node kernel layer 1 ----------------
__global__ void node1_kernel(const float* __restrict__ x, const int* __restrict__ tids,
                             const float* __restrict__ temb, const float* __restrict__ W1,
                             const float* __restrict__ a_s, const float* __restrict__ a_d) {
    __shared__ float Ws[21 * 64];
    __shared__ float xin[4][21];
    __shared__ float redS[8], redD[8];
    int t = threadIdx.x;
    for (int i = t; i < 21 * 64; i += 256) Ws[i] = W1[i];
    int ln = t >> 6, f = t & 63;
    int node = blockIdx.x * 4 + ln;
    if (node < N_NODES && f < 21) {
        if (f < 5) xin[ln][f] = x[node * 5 + f];
        else xin[ln][f] = temb[tids[node] * 16 + (f - 5)];
    }
    __syncthreads();
    int w = t >> 5;
    if (node < N_NODES) {
        float acc = 0.f;
#pragma unroll
        for (int j = 0; j < 21; j++) acc += xin[ln][j] * Ws[j * 64 + f];
        g_h[node * 64 + f] = acc;
        int head = f >> 5, c = f & 31;
        float ps = acc * a_s[head * 32 + c];
        float pd = acc * a_d[head * 32 + c];
#pragma unroll
        for (int o = 16; o; o >>= 1) {
            ps += __shfl_down_sync(0xFFFFFFFFu, ps, o);
            pd += __shfl_down_sync(0xFFFFFFFFu, pd, o);
        }
        if (c == 0) {
            g_als1[node * 2 + head] = ps;
            g_ald1[node * 2 + head] = pd;
            redS[w] = ps; redD[w] = pd;
        }
    } else if ((t & 31) == 0) {
        redS[w] = -1e30f; redD[w] = -1e30f;
    }
    __syncthreads();
    if (t < 4) {
        float* arr = (t < 2) ? redS : redD;
        int h = t & 1;
        float m = fmaxf(fmaxf(arr[h], arr[2 + h]), fmaxf(arr[4 + h], arr[6 + h]));
        atomicMax(&g_maxkey[t], fkey(m));
    }
}

// ---------------- aggregation layer 1: warp per dst, fused normalize+bias+relu ----------------
__global__ void agg1_kernel(const float* __restrict__ b1) {
    int warp = (blockIdx.x * blockDim.x + threadIdx.x) >> 5;
    int lane = threadIdx.x & 31;
    if (warp >= N_NODES) return;
    int node = warp;
    int head = lane >> 4;
    float M = leaky(funkey(g_maxkey[head]) + funkey(g_maxkey[2 + head]));
    float2 adp = *(const float2*)&g_ald1[node * 2];
    float ad = head ? adp.y : adp.x;
    // self loop
    float2 asp = *(const float2*)&g_als1[node * 2];
    float as = head ? asp.y : asp.x;
    float w = __expf(leaky(as + ad) - M);
    float2 hv = *(const float2*)&g_h[node * 64 + 2 * lane];
    float accx = w * hv.x, accy = w * hv.y, denom = w;
    int start = g_rowoff[node], end = g_rowoff[node + 1];
    for (int j0 = start; j0 < end; j0 += 32) {
        int n = min(32, end - j0);
        int my = (lane < n) ? __ldg(&g_csr[j0 + lane]) : 0;
        for (int k = 0; k < n; k++) {
            int src = __shfl_sync(0xFFFFFFFFu, my, k);
            float2 ap = *(const float2*)&g_als1[src * 2];
            float av = head ? ap.y : ap.x;
            float ww = __expf(leaky(av + ad) - M);
            float2 h2 = *(const float2*)&g_h[src * 64 + 2 * lane];
            accx += ww * h2.x; accy += ww * h2.y; denom += ww;
        }
    }
    float inv = 1.f / (denom + 1e-16f);
    float2 bb = *(const float2*)&b1[2 * lane];
    float2 o;
    o.x = fmaxf(accx * inv + bb.x, 0.f);
    o.y = fmaxf(accy * inv + bb.y, 0.f);
    *(float2*)&g_act[node * 64 + 2 * lane] = o;
}

// ---------------- node kernel layer 2 ----------------
__global__ void node2_kernel(const float* __restrict__ W2, const float* __restrict__ a_s2,
                             const float* __restrict__ a_d2) {
    __shared__ float Ws[64 * 64];
    __shared__ float xin[4][64];
    __shared__ float redS[8], redD[8];
    __shared__ float asv[4], adv[4];
    int t = threadIdx.x;
    for (int i = t; i < 64 * 64; i += 256) Ws[i] = W2[i];
    int ln = t >> 6, f = t & 63;
    int node = blockIdx.x * 4 + ln;
    if (node < N_NODES) xin[ln][f] = g_act[node * 64 + f];
    __syncthreads();
    float ps = 0.f, pd = 0.f;
    if (node < N_NODES) {
        float acc = 0.f;
#pragma unroll
        for (int j = 0; j < 64; j++) acc += xin[ln][j] * Ws[j * 64 + f];
        g_h[node * 64 + f] = acc;
        ps = acc * a_s2[f];
        pd = acc * a_d2[f];
    }
#pragma unroll
    for (int o = 16; o; o >>= 1) {
        ps += __shfl_down_sync(0xFFFFFFFFu, ps, o);
        pd += __shfl_down_sync(0xFFFFFFFFu, pd, o);
    }
    int w = t >> 5;
    if ((t & 31) == 0) { redS[w] = ps; redD[w] = pd; }
    __syncthreads();
    if (t < 4) {
        int nd = blockIdx.x * 4 + t;
        if (nd < N_NODES) {
            float as = redS[2 * t] + redS[2 * t + 1];
            float ad = redD[2 * t] + redD[2 * t + 1];
            g_als2[nd] = as; g_ald2[nd] = ad;
            asv[t] = as; adv[t] = ad;
        } else { asv[t] = -1e30f; adv[t] = -1e30f; }
    }
    __syncthreads();
    if (t == 0) {
        float ms = fmaxf(fmaxf(asv[0], asv[1]), fmaxf(asv[2], asv[3]));
        float md = fmaxf(fmaxf(adv[0], adv[1]), fmaxf(adv[2], adv[3]));
        atomicMax(&g_maxkey[4], fkey(ms));
        atomicMax(&g_maxkey[5], fkey(md));
    }
}

// ---------------- aggregation layer 2: warp per dst, fused normalize+bias+LayerNorm ----------------
__global__ void agg2_kernel(const float* __restrict__ b2, const float* __restrict__ gamma,
                            const float* __restrict__ beta, float* __restrict__ out) {
    int warp = (blockIdx.x * blockDim.x + threadIdx.x) >> 5;
    int lane = threadIdx.x & 31;
    if (warp >= N_NODES) return;
    int node = warp;
    float M = leaky(funkey(g_maxkey[4]) + funkey(g_maxkey[5]));
    float ad = __ldg(&g_ald2[node]);
    // self loop
    float w = __expf(leaky(__ldg(&g_als2[node]) + ad) - M);
    float2 hv = *(const float2*)&g_h[node * 64 + 2 * lane];
    float accx = w * hv.x, accy = w * hv.y, denom = w;
    int start = g_rowoff[node], end = g_rowoff[node + 1];
    for (int j0 = start; j0 < end; j0 += 32) {
        int n = min(32, end - j0);
        int my = (lane < n) ? __ldg(&g_csr[j0 + lane]) : 0;
        for (int k = 0; k < n; k++) {
            int src = __shfl_sync(0xFFFFFFFFu, my, k);
            float av = __ldg(&g_als2[src]);
            float ww = __expf(leaky(av + ad) - M);
            float2 h2 = *(const float2*)&g_h[src * 64 + 2 * lane];
            accx += ww * h2.x; accy += ww * h2.y; denom += ww;
        }
    }
    float inv = 1.f / (denom + 1e-16f);
    float2 bb = *(const float2*)&b2[2 * lane];
    float v0 = accx * inv + bb.x;
    float v1 = accy * inv + bb.y;
    // LayerNorm over the 64 values held by this warp (2/lane)
    float s = v0 + v1, q = v0 * v0 + v1 * v1;
#pragma unroll
    for (int o = 16; o; o >>= 1) {
        s += __shfl_xor_sync(0xFFFFFFFFu, s, o);
        q += __shfl_xor_sync(0xFFFFFFFFu, q, o);
    }
    float mu = s * (1.f / 64.f);
    float var = q * (1.f / 64.f) - mu * mu;
    float rinv = rsqrtf(var + 1e-5f);
    float2 gg = *(const float2*)&gamma[2 * lane];
    float2 be = *(const float2*)&beta[2 * lane];
    float2 o2;
    o2.x = (v0 - mu) * rinv * gg.x + be.x;
    o2.y = (v1 - mu) * rinv * gg.y + be.y;
    *(float2*)&out[node * 64 + 2 * lane] = o2;
}

// ---------------- launch ----------------
extern "C" void kernel_launch(void* const* d_in, const int* in_sizes, int n_in,
                              void* d_out, int out_size) {
    const float *x, *temb, *W1, *as1, *ad1, *b1, *W2, *as2, *ad2, *b2, *gamma, *beta;
    const int *ei, *tids;
    if (in_sizes[1] == 2 * N_EDGES) {
        x    = (const float*)d_in[0];
        ei   = (const int*)d_in[1];
        tids = (const int*)d_in[2];
        temb = (const float*)d_in[3];
        W1   = (const float*)d_in[4];
        as1  = (const float*)d_in[5];
        ad1  = (const float*)d_in[6];
        b1   = (const float*)d_in[7];
        W2   = (const float*)d_in[8];
        as2  = (const float*)d_in[9];
        ad2  = (const float*)d_in[10];
        b2   = (const float*)d_in[11];
        gamma= (const float*)d_in[12];
        beta = (const float*)d_in[13];
    } else {
        x    = (const float*)d_in[0];
        temb = (const float*)d_in[1];
        W1   = (const float*)d_in[2];
        as1  = (const float*)d_in[3];
        ad1  = (const float*)d_in[4];
        b1   = (const float*)d_in[5];
        W2   = (const float*)d_in[6];
        as2  = (const float*)d_in[7];
        ad2  = (const float*)d_in[8];
        b2   = (const float*)d_in[9];
        gamma= (const float*)d_in[10];
        beta = (const float*)d_in[11];
        ei   = (const int*)d_in[12];
        tids = (const int*)d_in[13];
    }
    float* out = (float*)d_out;

    const int nodeB  = (N_NODES + 255) / 256;
    const int edgeB  = (N_EDGES + 255) / 256;
    const int gemvB  = (N_NODES + 3) / 4;
    const int aggB   = (N_NODES * 32 + 255) / 256;

    zero_kernel<<<nodeB, 256>>>();
    hist_kernel<<<edgeB, 256>>>(ei);
    scan1_kernel<<<NCHUNK, SCHUNK>>>();
    scan2_kernel<<<1, 128>>>();
    scan3_kernel<<<nodeB, 256>>>();
    scatter_kernel<<<edgeB, 256>>>(ei);
    node1_kernel<<<gemvB, 256>>>(x, tids, temb, W1, as1, ad1);
    agg1_kernel<<<aggB, 256>>>(b1);
    node2_kernel<<<gemvB, 256>>>(W2, as2, ad2);
    agg2_kernel<<<aggB, 256>>>(b2, gamma, beta, out);
}

// round 6
// speedup vs baseline: 1.6057x; 1.0503x over previous
#include <cuda_runtime.h>
#include <cuda_bf16.h>
#include <cstdint>

#define N_NODES 100000
#define N_EDGES 3200000
#define SCHUNK 1024
#define NCHUNK ((N_NODES + SCHUNK - 1) / SCHUNK)

// ---------------- scratch (static device memory) ----------------
__device__ float g_h[N_NODES * 64];     // h (layer1), then h2 (layer2)
__device__ float g_act[N_NODES * 64];   // relu(out1)
__device__ float g_als1[N_NODES * 2];
__device__ float g_ald1[N_NODES * 2];
__device__ float g_als2[N_NODES];
__device__ float g_ald2[N_NODES];
__device__ unsigned g_maxkey[8];        // 0:s1h0 1:s1h1 2:d1h0 3:d1h1 4:s2 5:d2
__device__ int g_deg[N_NODES];
__device__ int g_rowoff[N_NODES + 1];
__device__ int g_cursor[N_NODES];
__device__ int g_csr[N_EDGES];          // src ids grouped by dst
__device__ int g_part[NCHUNK];

// ---------------- helpers ----------------
__device__ __forceinline__ float leaky(float x) { return x > 0.f ? x : 0.2f * x; }
__device__ __forceinline__ unsigned fkey(float f) {
    unsigned u = __float_as_uint(f);
    return (u & 0x80000000u) ? ~u : (u | 0x80000000u);
}
__device__ __forceinline__ float funkey(unsigned u) {
    return __uint_as_float((u & 0x80000000u) ? (u ^ 0x80000000u) : ~u);
}

// ---------------- CSR build ----------------
__global__ void zero_kernel() {
    int i = blockIdx.x * blockDim.x + threadIdx.x;
    if (i < N_NODES) g_deg[i] = 0;
    if (i < 8) g_maxkey[i] = 0u;
}
__global__ void hist_kernel(const int* __restrict__ ei) {
    int i = blockIdx.x * blockDim.x + threadIdx.x;
    if (i < N_EDGES) atomicAdd(&g_deg[__ldg(&ei[N_EDGES + i])], 1);
}
__global__ void scan1_kernel() {
    __shared__ int wsum[32];
    int t = threadIdx.x;
    int i = blockIdx.x * SCHUNK + t;
    int v = (i < N_NODES) ? g_deg[i] : 0;
    int x = v;
#pragma unroll
    for (int o = 1; o < 32; o <<= 1) {
        int y = __shfl_up_sync(0xFFFFFFFFu, x, o);
        if ((t & 31) >= o) x += y;
    }
    if ((t & 31) == 31) wsum[t >> 5] = x;
    __syncthreads();
    if (t < 32) {
        int y = wsum[t];
#pragma unroll
        for (int o = 1; o < 32; o <<= 1) {
            int z = __shfl_up_sync(0xFFFFFFFFu, y, o);
            if (t >= o) y += z;
        }
        wsum[t] = y;
    }
    __syncthreads();
    int base = (t >= 32) ? wsum[(t >> 5) - 1] : 0;
    int incl = x + base;
    if (i < N_NODES) g_rowoff[i] = incl - v;   // chunk-local exclusive
    if (t == SCHUNK - 1) g_part[blockIdx.x] = incl;
}
__global__ void scan2_kernel() {
    // parallel exclusive scan over NCHUNK (<=128) partial sums
    __shared__ int s[128];
    __shared__ int wtot[4];
    int t = threadIdx.x;
    int v = (t < NCHUNK) ? g_part[t] : 0;
    int x = v;
#pragma unroll
    for (int o = 1; o < 32; o <<= 1) {
        int y = __shfl_up_sync(0xFFFFFFFFu, x, o);
        if ((t & 31) >= o) x += y;
    }
    if ((t & 31) == 31) wtot[t >> 5] = x;
    __syncthreads();
    int base = 0;
    for (int w = 0; w < (t >> 5); w++) base += wtot[w];
    int incl = x + base;
    s[t] = incl - v;  // exclusive
    __syncthreads();
    if (t < NCHUNK) g_part[t] = s[t];
    if (t == 127) g_rowoff[N_NODES] = incl;
}
__global__ void scan3_kernel() {
    int i = blockIdx.x * blockDim.x + threadIdx.x;
    if (i < N_NODES) {
        int v = g_rowoff[i] + g_part[i >> 10];
        g_rowoff[i] = v;
        g_cursor[i] = v;
    }
}
__global__ void scatter_kernel(const int* __restrict__ ei) {
    int i = blockIdx.x * blockDim.x + threadIdx.x;
    if (i < N_EDGES) {
        int dst = __ldg(&ei[N_EDGES + i]);
        int pos = atomicAdd(&g_cursor[dst], 1);
        g_csr[pos] = __ldg(&ei[i]);
    }
}

// ---------------- node kernel layer 1 ----------------
__global__ void node1_kernel(const float* __restrict__ x, const int* __restrict__ tids,
                             const float* __restrict__ temb, const float* __restrict__ W1,
                             const float* __restrict__ a_s, const float* __restrict__ a_d) {
    __shared__ float Ws[21 * 64];
    __shared__ float xin[4][21];
    __shared__ float redS[8], redD[8];
    int t = threadIdx.x;
    for (int i = t; i < 21 * 64; i += 256) Ws[i] = W1[i];
    int ln = t >> 6, f = t & 63;
    int node = blockIdx.x * 4 + ln;
    if (node < N_NODES && f < 21) {
        if (f < 5) xin[ln][f] = x[node * 5 + f];
        else xin[ln][f] = temb[tids[node] * 16 + (f - 5)];
    }
    __syncthreads();
    int w = t >> 5;
    if (node < N_NODES) {
        float acc = 0.f;
#pragma unroll
        for (int j = 0; j < 21; j++) acc += xin[ln][j] * Ws[j * 64 + f];
        g_h[node * 64 + f] = acc;
        int head = f >> 5, c = f & 31;
        float ps = acc * a_s[head * 32 + c];
        float pd = acc * a_d[head * 32 + c];
#pragma unroll
        for (int o = 16; o; o >>= 1) {
            ps += __shfl_down_sync(0xFFFFFFFFu, ps, o);
            pd += __shfl_down_sync(0xFFFFFFFFu, pd, o);
        }
        if (c == 0) {
            g_als1[node * 2 + head] = ps;
            g_ald1[node * 2 + head] = pd;
            redS[w] = ps; redD[w] = pd;
        }
    } else if ((t & 31) == 0) {
        redS[w] = -1e30f; redD[w] = -1e30f;
    }
    __syncthreads();
    if (t < 4) {
        float* arr = (t < 2) ? redS : redD;
        int h = t & 1;
        float m = fmaxf(fmaxf(arr[h], arr[2 + h]), fmaxf(arr[4 + h], arr[6 + h]));
        atomicMax(&g_maxkey[t], fkey(m));
    }
}

// ---------------- aggregation layer 1: warp per dst, unrolled uniform loads ----------------
__global__ void agg1_kernel(const float* __restrict__ b1) {
    int warp = (blockIdx.x * blockDim.x + threadIdx.x) >> 5;
    int lane = threadIdx.x & 31;
    if (warp >= N_NODES) return;
    int node = warp;
    int head = lane >> 4;
    float M = leaky(funkey(g_maxkey[head]) + funkey(g_maxkey[2 + head]));
    float2 adp = *(const float2*)&g_ald1[node * 2];
    float ad = head ? adp.y : adp.x;
    // self loop
    float2 asp = *(const float2*)&g_als1[node * 2];
    float as = head ? asp.y : asp.x;
    float w = __expf(leaky(as + ad) - M);
    float2 hv = *(const float2*)&g_h[node * 64 + 2 * lane];
    float accx = w * hv.x, accy = w * hv.y, denom = w;
    int start = g_rowoff[node], end = g_rowoff[node + 1];
    int j = start;
    for (; j + 3 < end; j += 4) {
        int s0 = __ldg(&g_csr[j]);
        int s1 = __ldg(&g_csr[j + 1]);
        int s2 = __ldg(&g_csr[j + 2]);
        int s3 = __ldg(&g_csr[j + 3]);
        float2 a0 = *(const float2*)&g_als1[s0 * 2];
        float2 a1 = *(const float2*)&g_als1[s1 * 2];
        float2 a2 = *(const float2*)&g_als1[s2 * 2];
        float2 a3 = *(const float2*)&g_als1[s3 * 2];
        float2 h0 = *(const float2*)&g_h[s0 * 64 + 2 * lane];
        float2 h1 = *(const float2*)&g_h[s1 * 64 + 2 * lane];
        float2 h2 = *(const float2*)&g_h[s2 * 64 + 2 * lane];
        float2 h3 = *(const float2*)&g_h[s3 * 64 + 2 * lane];
        float w0 = __expf(leaky((head ? a0.y : a0.x) + ad) - M);
        float w1 = __expf(leaky((head ? a1.y : a1.x) + ad) - M);
        float w2 = __expf(leaky((head ? a2.y : a2.x) + ad) - M);
        float w3 = __expf(leaky((head ? a3.y : a3.x) + ad) - M);
        accx += w0 * h0.x; accy += w0 * h0.y;
        accx += w1 * h1.x; accy += w1 * h1.y;
        accx += w2 * h2.x; accy += w2 * h2.y;
        accx += w3 * h3.x; accy += w3 * h3.y;
        denom += w0 + w1 + w2 + w3;
    }
    for (; j < end; j++) {
        int s0 = __ldg(&g_csr[j]);
        float2 a0 = *(const float2*)&g_als1[s0 * 2];
        float2 h0 = *(const float2*)&g_h[s0 * 64 + 2 * lane];
        float w0 = __expf(leaky((head ? a0.y : a0.x) + ad) - M);
        accx += w0 * h0.x; accy += w0 * h0.y; denom += w0;
    }
    float inv = 1.f / (denom + 1e-16f);
    float2 bb = *(const float2*)&b1[2 * lane];
    float2 o;
    o.x = fmaxf(accx * inv + bb.x, 0.f);
    o.y = fmaxf(accy * inv + bb.y, 0.f);
    *(float2*)&g_act[node * 64 + 2 * lane] = o;
}

// ---------------- node kernel layer 2 ----------------
__global__ void node2_kernel(const float* __restrict__ W2, const float* __restrict__ a_s2,
                             const float* __restrict__ a_d2) {
    __shared__ float Ws[64 * 64];
    __shared__ float xin[4][64];
    __shared__ float redS[8], redD[8];
    __shared__ float asv[4], adv[4];
    int t = threadIdx.x;
    for (int i = t; i < 64 * 64; i += 256) Ws[i] = W2[i];
    int ln = t >> 6, f = t & 63;
    int node = blockIdx.x * 4 + ln;
    if (node < N_NODES) xin[ln][f] = g_act[node * 64 + f];
    __syncthreads();
    float ps = 0.f, pd = 0.f;
    if (node < N_NODES) {
        float acc = 0.f;
#pragma unroll
        for (int j = 0; j < 64; j++) acc += xin[ln][j] * Ws[j * 64 + f];
        g_h[node * 64 + f] = acc;
        ps = acc * a_s2[f];
        pd = acc * a_d2[f];
    }
#pragma unroll
    for (int o = 16; o; o >>= 1) {
        ps += __shfl_down_sync(0xFFFFFFFFu, ps, o);
        pd += __shfl_down_sync(0xFFFFFFFFu, pd, o);
    }
    int w = t >> 5;
    if ((t & 31) == 0) { redS[w] = ps; redD[w] = pd; }
    __syncthreads();
    if (t < 4) {
        int nd = blockIdx.x * 4 + t;
        if (nd < N_NODES) {
            float as = redS[2 * t] + redS[2 * t + 1];
            float ad = redD[2 * t] + redD[2 * t + 1];
            g_als2[nd] = as; g_ald2[nd] = ad;
            asv[t] = as; adv[t] = ad;
        } else { asv[t] = -1e30f; adv[t] = -1e30f; }
    }
    __syncthreads();
    if (t == 0) {
        float ms = fmaxf(fmaxf(asv[0], asv[1]), fmaxf(asv[2], asv[3]));
        float md = fmaxf(fmaxf(adv[0], adv[1]), fmaxf(adv[2], adv[3]));
        atomicMax(&g_maxkey[4], fkey(ms));
        atomicMax(&g_maxkey[5], fkey(md));
    }
}

// ---------------- aggregation layer 2: warp per dst, unrolled, fused LayerNorm ----------------
__global__ void agg2_kernel(const float* __restrict__ b2, const float* __restrict__ gamma,
                            const float* __restrict__ beta, float* __restrict__ out) {
    int warp = (blockIdx.x * blockDim.x + threadIdx.x) >> 5;
    int lane = threadIdx.x & 31;
    if (warp >= N_NODES) return;
    int node = warp;
    float M = leaky(funkey(g_maxkey[4]) + funkey(g_maxkey[5]));
    float ad = __ldg(&g_ald2[node]);
    // self loop
    float w = __expf(leaky(__ldg(&g_als2[node]) + ad) - M);
    float2 hv = *(const float2*)&g_h[node * 64 + 2 * lane];
    float accx = w * hv.x, accy = w * hv.y, denom = w;
    int start = g_rowoff[node], end = g_rowoff[node + 1];
    int j = start;
    for (; j + 3 < end; j += 4) {
        int s0 = __ldg(&g_csr[j]);
        int s1 = __ldg(&g_csr[j + 1]);
        int s2 = __ldg(&g_csr[j + 2]);
        int s3 = __ldg(&g_csr[j + 3]);
        float a0 = __ldg(&g_als2[s0]);
        float a1 = __ldg(&g_als2[s1]);
        float a2 = __ldg(&g_als2[s2]);
        float a3 = __ldg(&g_als2[s3]);
        float2 h0 = *(const float2*)&g_h[s0 * 64 + 2 * lane];
        float2 h1 = *(const float2*)&g_h[s1 * 64 + 2 * lane];
        float2 h2 = *(const float2*)&g_h[s2 * 64 + 2 * lane];
        float2 h3 = *(const float2*)&g_h[s3 * 64 + 2 * lane];
        float w0 = __expf(leaky(a0 + ad) - M);
        float w1 = __expf(leaky(a1 + ad) - M);
        float w2 = __expf(leaky(a2 + ad) - M);
        float w3 = __expf(leaky(a3 + ad) - M);
        accx += w0 * h0.x; accy += w0 * h0.y;
        accx += w1 * h1.x; accy += w1 * h1.y;
        accx += w2 * h2.x; accy += w2 * h2.y;
        accx += w3 * h3.x; accy += w3 * h3.y;
        denom += w0 + w1 + w2 + w3;
    }
    for (; j < end; j++) {
        int s0 = __ldg(&g_csr[j]);
        float a0 = __ldg(&g_als2[s0]);
        float2 h0 = *(const float2*)&g_h[s0 * 64 + 2 * lane];
        float w0 = __expf(leaky(a0 + ad) - M);
        accx += w0 * h0.x; accy += w0 * h0.y; denom += w0;
    }
    float inv = 1.f / (denom + 1e-16f);
    float2 bb = *(const float2*)&b2[2 * lane];
    float v0 = accx * inv + bb.x;
    float v1 = accy * inv + bb.y;
    // LayerNorm over the 64 values held by this warp (2/lane)
    float s = v0 + v1, q = v0 * v0 + v1 * v1;
#pragma unroll
    for (int o = 16; o; o >>= 1) {
        s += __shfl_xor_sync(0xFFFFFFFFu, s, o);
        q += __shfl_xor_sync(0xFFFFFFFFu, q, o);
    }
    float mu = s * (1.f / 64.f);
    float var = q * (1.f / 64.f) - mu * mu;
    float rinv = rsqrtf(var + 1e-5f);
    float2 gg = *(const float2*)&gamma[2 * lane];
    float2 be = *(const float2*)&beta[2 * lane];
    float2 o2;
    o2.x = (v0 - mu) * rinv * gg.x + be.x;
    o2.y = (v1 - mu) * rinv * gg.y + be.y;
    *(float2*)&out[node * 64 + 2 * lane] = o2;
}

// ---------------- launch ----------------
extern "C" void kernel_launch(void* const* d_in, const int* in_sizes, int n_in,
                              void* d_out, int out_size) {
    const float *x, *temb, *W1, *as1, *ad1, *b1, *W2, *as2, *ad2, *b2, *gamma, *beta;
    const int *ei, *tids;
    if (in_sizes[1] == 2 * N_EDGES) {
        x    = (const float*)d_in[0];
        ei   = (const int*)d_in[1];
        tids = (const int*)d_in[2];
        temb = (const float*)d_in[3];
        W1   = (const float*)d_in[4];
        as1  = (const float*)d_in[5];
        ad1  = (const float*)d_in[6];
        b1   = (const float*)d_in[7];
        W2   = (const float*)d_in[8];
        as2  = (const float*)d_in[9];
        ad2  = (const float*)d_in[10];
        b2   = (const float*)d_in[11];
        gamma= (const float*)d_in[12];
        beta = (const float*)d_in[13];
    } else {
        x    = (const float*)d_in[0];
        temb = (const float*)d_in[1];
        W1   = (const float*)d_in[2];
        as1  = (const float*)d_in[3];
        ad1  = (const float*)d_in[4];
        b1   = (const float*)d_in[5];
        W2   = (const float*)d_in[6];
        as2  = (const float*)d_in[7];
        ad2  = (const float*)d_in[8];
        b2   = (const float*)d_in[9];
        gamma= (const float*)d_in[10];
        beta = (const float*)d_in[11];
        ei   = (const int*)d_in[12];
        tids = (const int*)d_in[13];
    }
    float* out = (float*)d_out;

    const int nodeB  = (N_NODES + 255) / 256;
    const int edgeB  = (N_EDGES + 255) / 256;
    const int gemvB  = (N_NODES + 3) / 4;
    const int aggB   = (N_NODES * 32 + 255) / 256;

    zero_kernel<<<nodeB, 256>>>();
    hist_kernel<<<edgeB, 256>>>(ei);
    scan1_kernel<<<NCHUNK, SCHUNK>>>();
    scan2_kernel<<<1, 128>>>();
    scan3_kernel<<<nodeB, 256>>>();
    scatter_kernel<<<edgeB, 256>>>(ei);
    node1_kernel<<<gemvB, 256>>>(x, tids, temb, W1, as1, ad1);
    agg1_kernel<<<aggB, 256>>>(b1);
    node2_kernel<<<gemvB, 256>>>(W2, as2, ad2);
    agg2_kernel<<<aggB, 256>>>(b2, gamma, beta, out);
}

// round 8
// speedup vs baseline: 1.7976x; 1.1195x over previous
#include <cuda_runtime.h>
#include <cuda_bf16.h>
#include <cstdint>

#define N_NODES 100000
#define N_EDGES 3200000
#define SCHUNK 1024
#define NCHUNK ((N_NODES + SCHUNK - 1) / SCHUNK)

// ---------------- scratch (static device memory) ----------------
__device__ float g_h[N_NODES * 64];     // h (layer1), then h2 (layer2)
__device__ float g_act[N_NODES * 64];   // relu(out1)
__device__ float g_als1[N_NODES * 2];
__device__ float g_ald1[N_NODES * 2];
__device__ float g_als2[N_NODES];
__device__ float g_ald2[N_NODES];
__device__ unsigned g_maxkey[8];        // 0:s1h0 1:s1h1 2:d1h0 3:d1h1 4:s2 5:d2
__device__ int g_deg[N_NODES];
__device__ int g_rowoff[N_NODES + 1];
__device__ int g_cursor[N_NODES];
__device__ int g_csr[N_EDGES];          // src ids grouped by dst
__device__ int g_part[NCHUNK];

// ---------------- helpers ----------------
__device__ __forceinline__ float leaky(float x) { return x > 0.f ? x : 0.2f * x; }
__device__ __forceinline__ unsigned fkey(float f) {
    unsigned u = __float_as_uint(f);
    return (u & 0x80000000u) ? ~u : (u | 0x80000000u);
}
__device__ __forceinline__ float funkey(unsigned u) {
    return __uint_as_float((u & 0x80000000u) ? (u ^ 0x80000000u) : ~u);
}

// ---------------- CSR build ----------------
__global__ void zero_kernel() {
    int i = blockIdx.x * blockDim.x + threadIdx.x;
    if (i < N_NODES) g_deg[i] = 0;
    if (i < 8) g_maxkey[i] = 0u;
}
__global__ void hist_kernel(const int* __restrict__ ei) {
    int i = blockIdx.x * blockDim.x + threadIdx.x;
    if (i < N_EDGES) atomicAdd(&g_deg[__ldg(&ei[N_EDGES + i])], 1);
}
__global__ void scan1_kernel() {
    __shared__ int wsum[32];
    int t = threadIdx.x;
    int i = blockIdx.x * SCHUNK + t;
    int v = (i < N_NODES) ? g_deg[i] : 0;
    int x = v;
#pragma unroll
    for (int o = 1; o < 32; o <<= 1) {
        int y = __shfl_up_sync(0xFFFFFFFFu, x, o);
        if ((t & 31) >= o) x += y;
    }
    if ((t & 31) == 31) wsum[t >> 5] = x;
    __syncthreads();
    if (t < 32) {
        int y = wsum[t];
#pragma unroll
        for (int o = 1; o < 32; o <<= 1) {
            int z = __shfl_up_sync(0xFFFFFFFFu, y, o);
            if (t >= o) y += z;
        }
        wsum[t] = y;
    }
    __syncthreads();
    int base = (t >= 32) ? wsum[(t >> 5) - 1] : 0;
    int incl = x + base;
    if (i < N_NODES) g_rowoff[i] = incl - v;   // chunk-local exclusive
    if (t == SCHUNK - 1) g_part[blockIdx.x] = incl;
}
// merged scan2+scan3: each block prefixes the chunk partials in smem
__global__ void scan3_kernel() {
    __shared__ int sp[NCHUNK];
    __shared__ int sbase, stot;
    int t = threadIdx.x;
    if (t < NCHUNK) sp[t] = g_part[t];
    __syncthreads();
    if (t == 0) {
        int c = blockIdx.x >> 2;   // 256*4 = 1024-node chunks
        int b = 0, tot = 0;
        for (int k = 0; k < NCHUNK; k++) { if (k < c) b += sp[k]; tot += sp[k]; }
        sbase = b; stot = tot;
    }
    __syncthreads();
    int i = blockIdx.x * 256 + t;
    if (i < N_NODES) {
        int v = g_rowoff[i] + sbase;
        g_rowoff[i] = v;
        g_cursor[i] = v;
    }
    if (blockIdx.x == 0 && t == 0) g_rowoff[N_NODES] = stot;
}
__global__ void scatter_kernel(const int* __restrict__ ei) {
    int i = blockIdx.x * blockDim.x + threadIdx.x;
    if (i < N_EDGES) {
        int dst = __ldg(&ei[N_EDGES + i]);
        int pos = atomicAdd(&g_cursor[dst], 1);
        g_csr[pos] = __ldg(&ei[i]);
    }
}

// ---------------- node kernel layer 1 ----------------
__global__ void node1_kernel(const float* __restrict__ x, const int* __restrict__ tids,
                             const float* __restrict__ temb, const float* __restrict__ W1,
                             const float* __restrict__ a_s, const float* __restrict__ a_d) {
    __shared__ float Ws[21 * 64];
    __shared__ float xin[4][21];
    __shared__ float redS[8], redD[8];
    int t = threadIdx.x;
    for (int i = t; i < 21 * 64; i += 256) Ws[i] = W1[i];
    int ln = t >> 6, f = t & 63;
    int node = blockIdx.x * 4 + ln;
    if (node < N_NODES && f < 21) {
        if (f < 5) xin[ln][f] = x[node * 5 + f];
        else xin[ln][f] = temb[tids[node] * 16 + (f - 5)];
    }
    __syncthreads();
    int w = t >> 5;
    if (node < N_NODES) {
        float acc = 0.f;
#pragma unroll
        for (int j = 0; j < 21; j++) acc += xin[ln][j] * Ws[j * 64 + f];
        g_h[node * 64 + f] = acc;
        int head = f >> 5, c = f & 31;
        float ps = acc * a_s[head * 32 + c];
        float pd = acc * a_d[head * 32 + c];
#pragma unroll
        for (int o = 16; o; o >>= 1) {
            ps += __shfl_down_sync(0xFFFFFFFFu, ps, o);
            pd += __shfl_down_sync(0xFFFFFFFFu, pd, o);
        }
        if (c == 0) {
            g_als1[node * 2 + head] = ps;
            g_ald1[node * 2 + head] = pd;
            redS[w] = ps; redD[w] = pd;
        }
    } else if ((t & 31) == 0) {
        redS[w] = -1e30f; redD[w] = -1e30f;
    }
    __syncthreads();
    if (t < 4) {
        float* arr = (t < 2) ? redS : redD;
        int h = t & 1;
        float m = fmaxf(fmaxf(arr[h], arr[2 + h]), fmaxf(arr[4 + h], arr[6 + h]));
        atomicMax(&g_maxkey[t], fkey(m));
    }
}

// ---------------- aggregation layer 1: warp per dst, 2 edges in parallel (16 lanes each) ----------------
__global__ __launch_bounds__(256) void agg1_kernel(const float* __restrict__ b1) {
    int warp = (blockIdx.x * blockDim.x + threadIdx.x) >> 5;
    int lane = threadIdx.x & 31;
    if (warp >= N_NODES) return;
    int node = warp;
    int half = lane >> 4, sub = lane & 15;
    int head = sub >> 3;                    // channels 4*sub..4*sub+3 -> head = sub/8
    float M = leaky(funkey(g_maxkey[head]) + funkey(g_maxkey[2 + head]));
    float ad = __ldg(&g_ald1[node * 2 + head]);
    float4 acc = make_float4(0.f, 0.f, 0.f, 0.f);
    float denom = 0.f;
    if (half == 0) {   // self loop on half 0 only
        float as = __ldg(&g_als1[node * 2 + head]);
        float w = __expf(leaky(as + ad) - M);
        float4 hv = *(const float4*)&g_h[node * 64 + 4 * sub];
        acc.x = w * hv.x; acc.y = w * hv.y; acc.z = w * hv.z; acc.w = w * hv.w;
        denom = w;
    }
    int start = g_rowoff[node], end = g_rowoff[node + 1];
    int j0 = start;
    for (; j0 + 8 <= end; j0 += 8) {
        int j = j0 + half;
        int s0 = __ldg(&g_csr[j]);
        int s1 = __ldg(&g_csr[j + 2]);
        int s2 = __ldg(&g_csr[j + 4]);
        int s3 = __ldg(&g_csr[j + 6]);
        float a0 = __ldg(&g_als1[s0 * 2 + head]);
        float a1 = __ldg(&g_als1[s1 * 2 + head]);
        float a2 = __ldg(&g_als1[s2 * 2 + head]);
        float a3 = __ldg(&g_als1[s3 * 2 + head]);
        float4 h0 = *(const float4*)&g_h[s0 * 64 + 4 * sub];
        float4 h1 = *(const float4*)&g_h[s1 * 64 + 4 * sub];
        float4 h2 = *(const float4*)&g_h[s2 * 64 + 4 * sub];
        float4 h3 = *(const float4*)&g_h[s3 * 64 + 4 * sub];
        float w0 = __expf(leaky(a0 + ad) - M);
        float w1 = __expf(leaky(a1 + ad) - M);
        float w2 = __expf(leaky(a2 + ad) - M);
        float w3 = __expf(leaky(a3 + ad) - M);
        acc.x += w0 * h0.x; acc.y += w0 * h0.y; acc.z += w0 * h0.z; acc.w += w0 * h0.w;
        acc.x += w1 * h1.x; acc.y += w1 * h1.y; acc.z += w1 * h1.z; acc.w += w1 * h1.w;
        acc.x += w2 * h2.x; acc.y += w2 * h2.y; acc.z += w2 * h2.z; acc.w += w2 * h2.w;
        acc.x += w3 * h3.x; acc.y += w3 * h3.y; acc.z += w3 * h3.z; acc.w += w3 * h3.w;
        denom += w0 + w1 + w2 + w3;
    }
    for (int j = j0 + half; j < end; j += 2) {
        int s0 = __ldg(&g_csr[j]);
        float a0 = __ldg(&g_als1[s0 * 2 + head]);
        float4 h0 = *(const float4*)&g_h[s0 * 64 + 4 * sub];
        float w0 = __expf(leaky(a0 + ad) - M);
        acc.x += w0 * h0.x; acc.y += w0 * h0.y; acc.z += w0 * h0.z; acc.w += w0 * h0.w;
        denom += w0;
    }
    // combine halves
    acc.x += __shfl_xor_sync(0xFFFFFFFFu, acc.x, 16);
    acc.y += __shfl_xor_sync(0xFFFFFFFFu, acc.y, 16);
    acc.z += __shfl_xor_sync(0xFFFFFFFFu, acc.z, 16);
    acc.w += __shfl_xor_sync(0xFFFFFFFFu, acc.w, 16);
    denom += __shfl_xor_sync(0xFFFFFFFFu, denom, 16);
    if (half == 0) {
        float inv = 1.f / (denom + 1e-16f);
        float4 bb = *(const float4*)&b1[4 * sub];
        float4 o;
        o.x = fmaxf(acc.x * inv + bb.x, 0.f);
        o.y = fmaxf(acc.y * inv + bb.y, 0.f);
        o.z = fmaxf(acc.z * inv + bb.z, 0.f);
        o.w = fmaxf(acc.w * inv + bb.w, 0.f);
        *(float4*)&g_act[node * 64 + 4 * sub] = o;
    }
}

// ---------------- node kernel layer 2 ----------------
__global__ void node2_kernel(const float* __restrict__ W2, const float* __restrict__ a_s2,
                             const float* __restrict__ a_d2) {
    __shared__ float Ws[64 * 64];
    __shared__ float xin[4][64];
    __shared__ float redS[8], redD[8];
    __shared__ float asv[4], adv[4];
    int t = threadIdx.x;
    for (int i = t; i < 64 * 64; i += 256) Ws[i] = W2[i];
    int ln = t >> 6, f = t & 63;
    int node = blockIdx.x * 4 + ln;
    if (node < N_NODES) xin[ln][f] = g_act[node * 64 + f];
    __syncthreads();
    float ps = 0.f, pd = 0.f;
    if (node < N_NODES) {
        float acc = 0.f;
#pragma unroll
        for (int j = 0; j < 64; j++) acc += xin[ln][j] * Ws[j * 64 + f];
        g_h[node * 64 + f] = acc;
        ps = acc * a_s2[f];
        pd = acc * a_d2[f];
    }
#pragma unroll
    for (int o = 16; o; o >>= 1) {
        ps += __shfl_down_sync(0xFFFFFFFFu, ps, o);
        pd += __shfl_down_sync(0xFFFFFFFFu, pd, o);
    }
    int w = t >> 5;
    if ((t & 31) == 0) { redS[w] = ps; redD[w] = pd; }
    __syncthreads();
    if (t < 4) {
        int nd = blockIdx.x * 4 + t;
        if (nd < N_NODES) {
            float as = redS[2 * t] + redS[2 * t + 1];
            float ad = redD[2 * t] + redD[2 * t + 1];
            g_als2[nd] = as; g_ald2[nd] = ad;
            asv[t] = as; adv[t] = ad;
        } else { asv[t] = -1e30f; adv[t] = -1e30f; }
    }
    __syncthreads();
    if (t == 0) {
        float ms = fmaxf(fmaxf(asv[0], asv[1]), fmaxf(asv[2], asv[3]));
        float md = fmaxf(fmaxf(adv[0], adv[1]), fmaxf(adv[2], adv[3]));
        atomicMax(&g_maxkey[4], fkey(ms));
        atomicMax(&g_maxkey[5], fkey(md));
    }
}

// ---------------- aggregation layer 2: warp per dst, 2 edges in parallel, fused LayerNorm ----------------
__global__ __launch_bounds__(256) void agg2_kernel(const float* __restrict__ b2,
                                                   const float* __restrict__ gamma,
                                                   const float* __restrict__ beta,
                                                   float* __restrict__ out) {
    int warp = (blockIdx.x * blockDim.x + threadIdx.x) >> 5;
    int lane = threadIdx.x & 31;
    if (warp >= N_NODES) return;
    int node = warp;
    int half = lane >> 4, sub = lane & 15;
    float M = leaky(funkey(g_maxkey[4]) + funkey(g_maxkey[5]));
    float ad = __ldg(&g_ald2[node]);
    float4 acc = make_float4(0.f, 0.f, 0.f, 0.f);
    float denom = 0.f;
    if (half == 0) {
        float w = __expf(leaky(__ldg(&g_als2[node]) + ad) - M);
        float4 hv = *(const float4*)&g_h[node * 64 + 4 * sub];
        acc.x = w * hv.x; acc.y = w * hv.y; acc.z = w * hv.z; acc.w = w * hv.w;
        denom = w;
    }
    int start = g_rowoff[node], end = g_rowoff[node + 1];
    int j0 = start;
    for (; j0 + 8 <= end; j0 += 8) {
        int j = j0 + half;
        int s0 = __ldg(&g_csr[j]);
        int s1 = __ldg(&g_csr[j + 2]);
        int s2 = __ldg(&g_csr[j + 4]);
        int s3 = __ldg(&g_csr[j + 6]);
        float a0 = __ldg(&g_als2[s0]);
        float a1 = __ldg(&g_als2[s1]);
        float a2 = __ldg(&g_als2[s2]);
        float a3 = __ldg(&g_als2[s3]);
        float4 h0 = *(const float4*)&g_h[s0 * 64 + 4 * sub];
        float4 h1 = *(const float4*)&g_h[s1 * 64 + 4 * sub];
        float4 h2 = *(const float4*)&g_h[s2 * 64 + 4 * sub];
        float4 h3 = *(const float4*)&g_h[s3 * 64 + 4 * sub];
        float w0 = __expf(leaky(a0 + ad) - M);
        float w1 = __expf(leaky(a1 + ad) - M);
        float w2 = __expf(leaky(a2 + ad) - M);
        float w3 = __expf(leaky(a3 + ad) - M);
        acc.x += w0 * h0.x; acc.y += w0 * h0.y; acc.z += w0 * h0.z; acc.w += w0 * h0.w;
        acc.x += w1 * h1.x; acc.y += w1 * h1.y; acc.z += w1 * h1.z; acc.w += w1 * h1.w;
        acc.x += w2 * h2.x; acc.y += w2 * h2.y; acc.z += w2 * h2.z; acc.w += w2 * h2.w;
        acc.x += w3 * h3.x; acc.y += w3 * h3.y; acc.z += w3 * h3.z; acc.w += w3 * h3.w;
        denom += w0 + w1 + w2 + w3;
    }
    for (int j = j0 + half; j < end; j += 2) {
        int s0 = __ldg(&g_csr[j]);
        float a0 = __ldg(&g_als2[s0]);
        float4 h0 = *(const float4*)&g_h[s0 * 64 + 4 * sub];
        float w0 = __expf(leaky(a0 + ad) - M);
        acc.x += w0 * h0.x; acc.y += w0 * h0.y; acc.z += w0 * h0.z; acc.w += w0 * h0.w;
        denom += w0;
    }
    acc.x += __shfl_xor_sync(0xFFFFFFFFu, acc.x, 16);
    acc.y += __shfl_xor_sync(0xFFFFFFFFu, acc.y, 16);
    acc.z += __shfl_xor_sync(0xFFFFFFFFu, acc.z, 16);
    acc.w += __shfl_xor_sync(0xFFFFFFFFu, acc.w, 16);
    denom += __shfl_xor_sync(0xFFFFFFFFu, denom, 16);
    float inv = 1.f / (denom + 1e-16f);
    float4 bb = *(const float4*)&b2[4 * sub];
    float v0 = acc.x * inv + bb.x;
    float v1 = acc.y * inv + bb.y;
    float v2 = acc.z * inv + bb.z;
    float v3 = acc.w * inv + bb.w;
    // LayerNorm over 64 channels (4/lane, halves hold identical copies)
    float s = v0 + v1 + v2 + v3;
    float q = v0 * v0 + v1 * v1 + v2 * v2 + v3 * v3;
#pragma unroll
    for (int o = 8; o; o >>= 1) {
        s += __shfl_xor_sync(0xFFFFFFFFu, s, o);
        q += __shfl_xor_sync(0xFFFFFFFFu, q, o);
    }
    if (half == 0) {
        float mu = s * (1.f / 64.f);
        float var = q * (1.f / 64.f) - mu * mu;
        float rinv = rsqrtf(var + 1e-5f);
        float4 gg = *(const float4*)&gamma[4 * sub];
        float4 be = *(const float4*)&beta[4 * sub];
        float4 o2;
        o2.x = (v0 - mu) * rinv * gg.x + be.x;
        o2.y = (v1 - mu) * rinv * gg.y + be.y;
        o2.z = (v2 - mu) * rinv * gg.z + be.z;
        o2.w = (v3 - mu) * rinv * gg.w + be.w;
        *(float4*)&out[node * 64 + 4 * sub] = o2;
    }
}

// ---------------- launch ----------------
extern "C" void kernel_launch(void* const* d_in, const int* in_sizes, int n_in,
                              void* d_out, int out_size) {
    const float *x, *temb, *W1, *as1, *ad1, *b1, *W2, *as2, *ad2, *b2, *gamma, *beta;
    const int *ei, *tids;
    if (in_sizes[1] == 2 * N_EDGES) {
        x    = (const float*)d_in[0];
        ei   = (const int*)d_in[1];
        tids = (const int*)d_in[2];
        temb = (const float*)d_in[3];
        W1   = (const float*)d_in[4];
        as1  = (const float*)d_in[5];
        ad1  = (const float*)d_in[6];
        b1   = (const float*)d_in[7];
        W2   = (const float*)d_in[8];
        as2  = (const float*)d_in[9];
        ad2  = (const float*)d_in[10];
        b2   = (const float*)d_in[11];
        gamma= (const float*)d_in[12];
        beta = (const float*)d_in[13];
    } else {
        x    = (const float*)d_in[0];
        temb = (const float*)d_in[1];
        W1   = (const float*)d_in[2];
        as1  = (const float*)d_in[3];
        ad1  = (const float*)d_in[4];
        b1   = (const float*)d_in[5];
        W2   = (const float*)d_in[6];
        as2  = (const float*)d_in[7];
        ad2  = (const float*)d_in[8];
        b2   = (const float*)d_in[9];
        gamma= (const float*)d_in[10];
        beta = (const float*)d_in[11];
        ei   = (const int*)d_in[12];
        tids = (const int*)d_in[13];
    }
    float* out = (float*)d_out;

    const int nodeB  = (N_NODES + 255) / 256;
    const int edgeB  = (N_EDGES + 255) / 256;
    const int gemvB  = (N_NODES + 3) / 4;
    const int aggB   = (N_NODES * 32 + 255) / 256;

    zero_kernel<<<nodeB, 256>>>();
    hist_kernel<<<edgeB, 256>>>(ei);
    scan1_kernel<<<NCHUNK, SCHUNK>>>();
    scan3_kernel<<<nodeB, 256>>>();
    scatter_kernel<<<edgeB, 256>>>(ei);
    node1_kernel<<<gemvB, 256>>>(x, tids, temb, W1, as1, ad1);
    agg1_kernel<<<aggB, 256>>>(b1);
    node2_kernel<<<gemvB, 256>>>(W2, as2, ad2);
    agg2_kernel<<<aggB, 256>>>(b2, gamma, beta, out);
}

// round 9
// speedup vs baseline: 1.8501x; 1.0292x over previous
#include <cuda_runtime.h>
#include <cuda_fp16.h>
#include <cstdint>

#define N_NODES 100000
#define N_EDGES 3200000
#define SCHUNK 1024
#define NCHUNK ((N_NODES + SCHUNK - 1) / SCHUNK)

// ---------------- scratch (static device memory) ----------------
__device__ uint4 g_h16[N_NODES * 8];    // h as fp16, 64 ch = 128 B/node (layer1 then layer2)
__device__ float g_act[N_NODES * 64];   // relu(out1), fp32 for node2 GEMV
__device__ float g_als1[N_NODES * 2];
__device__ float g_ald1[N_NODES * 2];
__device__ float g_als2[N_NODES];
__device__ float g_ald2[N_NODES];
__device__ unsigned g_maxkey[8];        // 0:s1h0 1:s1h1 2:d1h0 3:d1h1 4:s2 5:d2
__device__ int g_deg[N_NODES];
__device__ int g_rowoff[N_NODES + 1];
__device__ int g_cursor[N_NODES];
__device__ int g_csr[N_EDGES];          // src ids grouped by dst
__device__ int g_part[NCHUNK];

// ---------------- helpers ----------------
__device__ __forceinline__ float leaky(float x) { return x > 0.f ? x : 0.2f * x; }
__device__ __forceinline__ unsigned fkey(float f) {
    unsigned u = __float_as_uint(f);
    return (u & 0x80000000u) ? ~u : (u | 0x80000000u);
}
__device__ __forceinline__ float funkey(unsigned u) {
    return __uint_as_float((u & 0x80000000u) ? (u ^ 0x80000000u) : ~u);
}
__device__ __forceinline__ void acc8(float* a, uint4 hv, float w) {
    __half2* hp = reinterpret_cast<__half2*>(&hv);
#pragma unroll
    for (int i = 0; i < 4; i++) {
        float2 p = __half22float2(hp[i]);
        a[2 * i]     += w * p.x;
        a[2 * i + 1] += w * p.y;
    }
}

// ---------------- CSR build ----------------
__global__ void zero_kernel() {
    int i = blockIdx.x * blockDim.x + threadIdx.x;
    if (i < N_NODES) g_deg[i] = 0;
    if (i < 8) g_maxkey[i] = 0u;
}
__global__ void hist_kernel(const int* __restrict__ ei) {
    int i = blockIdx.x * blockDim.x + threadIdx.x;
    if (i < N_EDGES) atomicAdd(&g_deg[__ldg(&ei[N_EDGES + i])], 1);
}
__global__ void scan1_kernel() {
    __shared__ int wsum[32];
    int t = threadIdx.x;
    int i = blockIdx.x * SCHUNK + t;
    int v = (i < N_NODES) ? g_deg[i] : 0;
    int x = v;
#pragma unroll
    for (int o = 1; o < 32; o <<= 1) {
        int y = __shfl_up_sync(0xFFFFFFFFu, x, o);
        if ((t & 31) >= o) x += y;
    }
    if ((t & 31) == 31) wsum[t >> 5] = x;
    __syncthreads();
    if (t < 32) {
        int y = wsum[t];
#pragma unroll
        for (int o = 1; o < 32; o <<= 1) {
            int z = __shfl_up_sync(0xFFFFFFFFu, y, o);
            if (t >= o) y += z;
        }
        wsum[t] = y;
    }
    __syncthreads();
    int base = (t >= 32) ? wsum[(t >> 5) - 1] : 0;
    int incl = x + base;
    if (i < N_NODES) g_rowoff[i] = incl - v;   // chunk-local exclusive
    if (t == SCHUNK - 1) g_part[blockIdx.x] = incl;
}
// merged scan2+scan3: each block prefixes the chunk partials in smem
__global__ void scan3_kernel() {
    __shared__ int sp[NCHUNK];
    __shared__ int sbase, stot;
    int t = threadIdx.x;
    if (t < NCHUNK) sp[t] = g_part[t];
    __syncthreads();
    if (t == 0) {
        int c = blockIdx.x >> 2;   // 256*4 = 1024-node chunks
        int b = 0, tot = 0;
        for (int k = 0; k < NCHUNK; k++) { if (k < c) b += sp[k]; tot += sp[k]; }
        sbase = b; stot = tot;
    }
    __syncthreads();
    int i = blockIdx.x * 256 + t;
    if (i < N_NODES) {
        int v = g_rowoff[i] + sbase;
        g_rowoff[i] = v;
        g_cursor[i] = v;
    }
    if (blockIdx.x == 0 && t == 0) g_rowoff[N_NODES] = stot;
}
__global__ void scatter_kernel(const int* __restrict__ ei) {
    int i = blockIdx.x * blockDim.x + threadIdx.x;
    if (i < N_EDGES) {
        int dst = __ldg(&ei[N_EDGES + i]);
        int pos = atomicAdd(&g_cursor[dst], 1);
        g_csr[pos] = __ldg(&ei[i]);
    }
}

// ---------------- node kernel layer 1 ----------------
__global__ void node1_kernel(const float* __restrict__ x, const int* __restrict__ tids,
                             const float* __restrict__ temb, const float* __restrict__ W1,
                             const float* __restrict__ a_s, const float* __restrict__ a_d) {
    __shared__ float Ws[21 * 64];
    __shared__ float xin[4][21];
    __shared__ float redS[8], redD[8];
    int t = threadIdx.x;
    for (int i = t; i < 21 * 64; i += 256) Ws[i] = W1[i];
    int ln = t >> 6, f = t & 63;
    int node = blockIdx.x * 4 + ln;
    if (node < N_NODES && f < 21) {
        if (f < 5) xin[ln][f] = x[node * 5 + f];
        else xin[ln][f] = temb[tids[node] * 16 + (f - 5)];
    }
    __syncthreads();
    int w = t >> 5;
    if (node < N_NODES) {
        float acc = 0.f;
#pragma unroll
        for (int j = 0; j < 21; j++) acc += xin[ln][j] * Ws[j * 64 + f];
        reinterpret_cast<__half*>(g_h16)[node * 64 + f] = __float2half(acc);
        int head = f >> 5, c = f & 31;
        float ps = acc * a_s[head * 32 + c];
        float pd = acc * a_d[head * 32 + c];
#pragma unroll
        for (int o = 16; o; o >>= 1) {
            ps += __shfl_down_sync(0xFFFFFFFFu, ps, o);
            pd += __shfl_down_sync(0xFFFFFFFFu, pd, o);
        }
        if (c == 0) {
            g_als1[node * 2 + head] = ps;
            g_ald1[node * 2 + head] = pd;
            redS[w] = ps; redD[w] = pd;
        }
    } else if ((t & 31) == 0) {
        redS[w] = -1e30f; redD[w] = -1e30f;
    }
    __syncthreads();
    if (t < 4) {
        float* arr = (t < 2) ? redS : redD;
        int h = t & 1;
        float m = fmaxf(fmaxf(arr[h], arr[2 + h]), fmaxf(arr[4 + h], arr[6 + h]));
        atomicMax(&g_maxkey[t], fkey(m));
    }
}

// ---------------- aggregation layer 1: warp per dst, 4 edges in parallel (8 lanes each) ----------------
__global__ __launch_bounds__(256) void agg1_kernel(const float* __restrict__ b1) {
    int warp = (blockIdx.x * blockDim.x + threadIdx.x) >> 5;
    int lane = threadIdx.x & 31;
    if (warp >= N_NODES) return;
    int node = warp;
    int quarter = lane >> 3, sub = lane & 7;
    int head = sub >> 2;                    // channels 8*sub..8*sub+7 -> head = sub/4
    float M = leaky(funkey(g_maxkey[head]) + funkey(g_maxkey[2 + head]));
    float ad = __ldg(&g_ald1[node * 2 + head]);
    float a[8] = {0.f, 0.f, 0.f, 0.f, 0.f, 0.f, 0.f, 0.f};
    float denom = 0.f;
    if (quarter == 0) {   // self loop
        float as = __ldg(&g_als1[node * 2 + head]);
        float w = __expf(leaky(as + ad) - M);
        uint4 hv = __ldg(&g_h16[node * 8 + sub]);
        acc8(a, hv, w);
        denom = w;
    }
    int start = g_rowoff[node], end = g_rowoff[node + 1];
    int j0 = start;
    for (; j0 + 16 <= end; j0 += 16) {
        int j = j0 + quarter;
        int s0 = __ldg(&g_csr[j]);
        int s1 = __ldg(&g_csr[j + 4]);
        int s2 = __ldg(&g_csr[j + 8]);
        int s3 = __ldg(&g_csr[j + 12]);
        float a0 = __ldg(&g_als1[s0 * 2 + head]);
        float a1 = __ldg(&g_als1[s1 * 2 + head]);
        float a2 = __ldg(&g_als1[s2 * 2 + head]);
        float a3 = __ldg(&g_als1[s3 * 2 + head]);
        uint4 h0 = __ldg(&g_h16[s0 * 8 + sub]);
        uint4 h1 = __ldg(&g_h16[s1 * 8 + sub]);
        uint4 h2 = __ldg(&g_h16[s2 * 8 + sub]);
        uint4 h3 = __ldg(&g_h16[s3 * 8 + sub]);
        float w0 = __expf(leaky(a0 + ad) - M);
        float w1 = __expf(leaky(a1 + ad) - M);
        float w2 = __expf(leaky(a2 + ad) - M);
        float w3 = __expf(leaky(a3 + ad) - M);
        acc8(a, h0, w0); acc8(a, h1, w1); acc8(a, h2, w2); acc8(a, h3, w3);
        denom += w0 + w1 + w2 + w3;
    }
    for (int j = j0 + quarter; j < end; j += 4) {
        int s0 = __ldg(&g_csr[j]);
        float a0 = __ldg(&g_als1[s0 * 2 + head]);
        uint4 h0 = __ldg(&g_h16[s0 * 8 + sub]);
        float w0 = __expf(leaky(a0 + ad) - M);
        acc8(a, h0, w0);
        denom += w0;
    }
    // combine quarters (lane bits 3 and 4)
#pragma unroll
    for (int i = 0; i < 8; i++) {
        a[i] += __shfl_xor_sync(0xFFFFFFFFu, a[i], 8);
        a[i] += __shfl_xor_sync(0xFFFFFFFFu, a[i], 16);
    }
    denom += __shfl_xor_sync(0xFFFFFFFFu, denom, 8);
    denom += __shfl_xor_sync(0xFFFFFFFFu, denom, 16);
    if (quarter == 0) {
        float inv = 1.f / (denom + 1e-16f);
        float4 b0 = *(const float4*)&b1[8 * sub];
        float4 b4 = *(const float4*)&b1[8 * sub + 4];
        float4 o0, o1;
        o0.x = fmaxf(a[0] * inv + b0.x, 0.f);
        o0.y = fmaxf(a[1] * inv + b0.y, 0.f);
        o0.z = fmaxf(a[2] * inv + b0.z, 0.f);
        o0.w = fmaxf(a[3] * inv + b0.w, 0.f);
        o1.x = fmaxf(a[4] * inv + b4.x, 0.f);
        o1.y = fmaxf(a[5] * inv + b4.y, 0.f);
        o1.z = fmaxf(a[6] * inv + b4.z, 0.f);
        o1.w = fmaxf(a[7] * inv + b4.w, 0.f);
        *(float4*)&g_act[node * 64 + 8 * sub] = o0;
        *(float4*)&g_act[node * 64 + 8 * sub + 4] = o1;
    }
}

// ---------------- node kernel layer 2 ----------------
__global__ void node2_kernel(const float* __restrict__ W2, const float* __restrict__ a_s2,
                             const float* __restrict__ a_d2) {
    __shared__ float Ws[64 * 64];
    __shared__ float xin[4][64];
    __shared__ float redS[8], redD[8];
    __shared__ float asv[4], adv[4];
    int t = threadIdx.x;
    for (int i = t; i < 64 * 64; i += 256) Ws[i] = W2[i];
    int ln = t >> 6, f = t & 63;
    int node = blockIdx.x * 4 + ln;
    if (node < N_NODES) xin[ln][f] = g_act[node * 64 + f];
    __syncthreads();
    float ps = 0.f, pd = 0.f;
    if (node < N_NODES) {
        float acc = 0.f;
#pragma unroll
        for (int j = 0; j < 64; j++) acc += xin[ln][j] * Ws[j * 64 + f];
        reinterpret_cast<__half*>(g_h16)[node * 64 + f] = __float2half(acc);
        ps = acc * a_s2[f];
        pd = acc * a_d2[f];
    }
#pragma unroll
    for (int o = 16; o; o >>= 1) {
        ps += __shfl_down_sync(0xFFFFFFFFu, ps, o);
        pd += __shfl_down_sync(0xFFFFFFFFu, pd, o);
    }
    int w = t >> 5;
    if ((t & 31) == 0) { redS[w] = ps; redD[w] = pd; }
    __syncthreads();
    if (t < 4) {
        int nd = blockIdx.x * 4 + t;
        if (nd < N_NODES) {
            float as = redS[2 * t] + redS[2 * t + 1];
            float ad = redD[2 * t] + redD[2 * t + 1];
            g_als2[nd] = as; g_ald2[nd] = ad;
            asv[t] = as; adv[t] = ad;
        } else { asv[t] = -1e30f; adv[t] = -1e30f; }
    }
    __syncthreads();
    if (t == 0) {
        float ms = fmaxf(fmaxf(asv[0], asv[1]), fmaxf(asv[2], asv[3]));
        float md = fmaxf(fmaxf(adv[0], adv[1]), fmaxf(adv[2], adv[3]));
        atomicMax(&g_maxkey[4], fkey(ms));
        atomicMax(&g_maxkey[5], fkey(md));
    }
}

// ---------------- aggregation layer 2: warp per dst, 4 edges in parallel, fused LayerNorm ----------------
__global__ __launch_bounds__(256) void agg2_kernel(const float* __restrict__ b2,
                                                   const float* __restrict__ gamma,
                                                   const float* __restrict__ beta,
                                                   float* __restrict__ out) {
    int warp = (blockIdx.x * blockDim.x + threadIdx.x) >> 5;
    int lane = threadIdx.x & 31;
    if (warp >= N_NODES) return;
    int node = warp;
    int quarter = lane >> 3, sub = lane & 7;
    float M = leaky(funkey(g_maxkey[4]) + funkey(g_maxkey[5]));
    float ad = __ldg(&g_ald2[node]);
    float a[8] = {0.f, 0.f, 0.f, 0.f, 0.f, 0.f, 0.f, 0.f};
    float denom = 0.f;
    if (quarter == 0) {
        float w = __expf(leaky(__ldg(&g_als2[node]) + ad) - M);
        uint4 hv = __ldg(&g_h16[node * 8 + sub]);
        acc8(a, hv, w);
        denom = w;
    }
    int start = g_rowoff[node], end = g_rowoff[node + 1];
    int j0 = start;
    for (; j0 + 16 <= end; j0 += 16) {
        int j = j0 + quarter;
        int s0 = __ldg(&g_csr[j]);
        int s1 = __ldg(&g_csr[j + 4]);
        int s2 = __ldg(&g_csr[j + 8]);
        int s3 = __ldg(&g_csr[j + 12]);
        float a0 = __ldg(&g_als2[s0]);
        float a1 = __ldg(&g_als2[s1]);
        float a2 = __ldg(&g_als2[s2]);
        float a3 = __ldg(&g_als2[s3]);
        uint4 h0 = __ldg(&g_h16[s0 * 8 + sub]);
        uint4 h1 = __ldg(&g_h16[s1 * 8 + sub]);
        uint4 h2 = __ldg(&g_h16[s2 * 8 + sub]);
        uint4 h3 = __ldg(&g_h16[s3 * 8 + sub]);
        float w0 = __expf(leaky(a0 + ad) - M);
        float w1 = __expf(leaky(a1 + ad) - M);
        float w2 = __expf(leaky(a2 + ad) - M);
        float w3 = __expf(leaky(a3 + ad) - M);
        acc8(a, h0, w0); acc8(a, h1, w1); acc8(a, h2, w2); acc8(a, h3, w3);
        denom += w0 + w1 + w2 + w3;
    }
    for (int j = j0 + quarter; j < end; j += 4) {
        int s0 = __ldg(&g_csr[j]);
        float a0 = __ldg(&g_als2[s0]);
        uint4 h0 = __ldg(&g_h16[s0 * 8 + sub]);
        float w0 = __expf(leaky(a0 + ad) - M);
        acc8(a, h0, w0);
        denom += w0;
    }
#pragma unroll
    for (int i = 0; i < 8; i++) {
        a[i] += __shfl_xor_sync(0xFFFFFFFFu, a[i], 8);
        a[i] += __shfl_xor_sync(0xFFFFFFFFu, a[i], 16);
    }
    denom += __shfl_xor_sync(0xFFFFFFFFu, denom, 8);
    denom += __shfl_xor_sync(0xFFFFFFFFu, denom, 16);
    float inv = 1.f / (denom + 1e-16f);
    float4 b0 = *(const float4*)&b2[8 * sub];
    float4 b4 = *(const float4*)&b2[8 * sub + 4];
    float v[8];
    v[0] = a[0] * inv + b0.x; v[1] = a[1] * inv + b0.y;
    v[2] = a[2] * inv + b0.z; v[3] = a[3] * inv + b0.w;
    v[4] = a[4] * inv + b4.x; v[5] = a[5] * inv + b4.y;
    v[6] = a[6] * inv + b4.z; v[7] = a[7] * inv + b4.w;
    // LayerNorm over 64 channels (8/lane across 8 sub-lanes; quarters identical)
    float s = 0.f, q = 0.f;
#pragma unroll
    for (int i = 0; i < 8; i++) { s += v[i]; q += v[i] * v[i]; }
#pragma unroll
    for (int o = 4; o; o >>= 1) {
        s += __shfl_xor_sync(0xFFFFFFFFu, s, o);
        q += __shfl_xor_sync(0xFFFFFFFFu, q, o);
    }
    if (quarter == 0) {
        float mu = s * (1.f / 64.f);
        float var = q * (1.f / 64.f) - mu * mu;
        float rinv = rsqrtf(var + 1e-5f);
        float4 g0 = *(const float4*)&gamma[8 * sub];
        float4 g4 = *(const float4*)&gamma[8 * sub + 4];
        float4 e0 = *(const float4*)&beta[8 * sub];
        float4 e4 = *(const float4*)&beta[8 * sub + 4];
        float4 o0, o1;
        o0.x = (v[0] - mu) * rinv * g0.x + e0.x;
        o0.y = (v[1] - mu) * rinv * g0.y + e0.y;
        o0.z = (v[2] - mu) * rinv * g0.z + e0.z;
        o0.w = (v[3] - mu) * rinv * g0.w + e0.w;
        o1.x = (v[4] - mu) * rinv * g4.x + e4.x;
        o1.y = (v[5] - mu) * rinv * g4.y + e4.y;
        o1.z = (v[6] - mu) * rinv * g4.z + e4.z;
        o1.w = (v[7] - mu) * rinv * g4.w + e4.w;
        *(float4*)&out[node * 64 + 8 * sub] = o0;
        *(float4*)&out[node * 64 + 8 * sub + 4] = o1;
    }
}

// ---------------- launch ----------------
extern "C" void kernel_launch(void* const* d_in, const int* in_sizes, int n_in,
                              void* d_out, int out_size) {
    const float *x, *temb, *W1, *as1, *ad1, *b1, *W2, *as2, *ad2, *b2, *gamma, *beta;
    const int *ei, *tids;
    if (in_sizes[1] == 2 * N_EDGES) {
        x    = (const float*)d_in[0];
        ei   = (const int*)d_in[1];
        tids = (const int*)d_in[2];
        temb = (const float*)d_in[3];
        W1   = (const float*)d_in[4];
        as1  = (const float*)d_in[5];
        ad1  = (const float*)d_in[6];
        b1   = (const float*)d_in[7];
        W2   = (const float*)d_in[8];
        as2  = (const float*)d_in[9];
        ad2  = (const float*)d_in[10];
        b2   = (const float*)d_in[11];
        gamma= (const float*)d_in[12];
        beta = (const float*)d_in[13];
    } else {
        x    = (const float*)d_in[0];
        temb = (const float*)d_in[1];
        W1   = (const float*)d_in[2];
        as1  = (const float*)d_in[3];
        ad1  = (const float*)d_in[4];
        b1   = (const float*)d_in[5];
        W2   = (const float*)d_in[6];
        as2  = (const float*)d_in[7];
        ad2  = (const float*)d_in[8];
        b2   = (const float*)d_in[9];
        gamma= (const float*)d_in[10];
        beta = (const float*)d_in[11];
        ei   = (const int*)d_in[12];
        tids = (const int*)d_in[13];
    }
    float* out = (float*)d_out;

    const int nodeB  = (N_NODES + 255) / 256;
    const int edgeB  = (N_EDGES + 255) / 256;
    const int gemvB  = (N_NODES + 3) / 4;
    const int aggB   = (N_NODES * 32 + 255) / 256;

    zero_kernel<<<nodeB, 256>>>();
    hist_kernel<<<edgeB, 256>>>(ei);
    scan1_kernel<<<NCHUNK, SCHUNK>>>();
    scan3_kernel<<<nodeB, 256>>>();
    scatter_kernel<<<edgeB, 256>>>(ei);
    node1_kernel<<<gemvB, 256>>>(x, tids, temb, W1, as1, ad1);
    agg1_kernel<<<aggB, 256>>>(b1);
    node2_kernel<<<gemvB, 256>>>(W2, as2, ad2);
    agg2_kernel<<<aggB, 256>>>(b2, gamma, beta, out);
}

// round 14
// speedup vs baseline: 1.8700x; 1.0108x over previous
#include <cuda_runtime.h>
#include <cuda_fp16.h>
#include <cstdint>

#define N_NODES 100000
#define N_EDGES 3200000
#define SCHUNK 1024
#define NCHUNK ((N_NODES + SCHUNK - 1) / SCHUNK)

// ---------------- scratch (static device memory) ----------------
__device__ uint4 g_h16[N_NODES * 8];    // h as fp16, 64 ch = 128 B/node (layer1 then layer2)
__device__ float g_act[N_NODES * 64];   // relu(out1), fp32 for node2 GEMV
__device__ float g_als1[N_NODES * 2];
__device__ float g_ald1[N_NODES * 2];
__device__ float g_als2[N_NODES];
__device__ float g_ald2[N_NODES];
__device__ unsigned g_maxkey[8];        // 0:s1h0 1:s1h1 2:d1h0 3:d1h1 4:s2 5:d2
__device__ int g_deg[N_NODES];
__device__ int g_rowoff[N_NODES + 1];
__device__ int g_cursor[N_NODES];
__device__ int g_csr[N_EDGES];          // src ids grouped by dst
__device__ int g_part[NCHUNK];

// ---------------- helpers ----------------
__device__ __forceinline__ float leaky(float x) { return x > 0.f ? x : 0.2f * x; }
__device__ __forceinline__ unsigned fkey(float f) {
    unsigned u = __float_as_uint(f);
    return (u & 0x80000000u) ? ~u : (u | 0x80000000u);
}
__device__ __forceinline__ float funkey(unsigned u) {
    return __uint_as_float((u & 0x80000000u) ? (u ^ 0x80000000u) : ~u);
}
__device__ __forceinline__ void acc8(float* a, uint4 hv, float w) {
    __half2* hp = reinterpret_cast<__half2*>(&hv);
#pragma unroll
    for (int i = 0; i < 4; i++) {
        float2 p = __half22float2(hp[i]);
        a[2 * i]     += w * p.x;
        a[2 * i + 1] += w * p.y;
    }
}

// ---------------- CSR build ----------------
__global__ void zero_kernel() {
    int i = blockIdx.x * blockDim.x + threadIdx.x;
    if (i < N_NODES) g_deg[i] = 0;
    if (i < 8) g_maxkey[i] = 0u;
}
__global__ void hist_kernel(const int* __restrict__ ei) {
    int i = blockIdx.x * blockDim.x + threadIdx.x;
    if (i < N_EDGES) atomicAdd(&g_deg[__ldg(&ei[N_EDGES + i])], 1);
}
__global__ void scan1_kernel() {
    __shared__ int wsum[32];
    int t = threadIdx.x;
    int i = blockIdx.x * SCHUNK + t;
    int v = (i < N_NODES) ? g_deg[i] : 0;
    int x = v;
#pragma unroll
    for (int o = 1; o < 32; o <<= 1) {
        int y = __shfl_up_sync(0xFFFFFFFFu, x, o);
        if ((t & 31) >= o) x += y;
    }
    if ((t & 31) == 31) wsum[t >> 5] = x;
    __syncthreads();
    if (t < 32) {
        int y = wsum[t];
#pragma unroll
        for (int o = 1; o < 32; o <<= 1) {
            int z = __shfl_up_sync(0xFFFFFFFFu, y, o);
            if (t >= o) y += z;
        }
        wsum[t] = y;
    }
    __syncthreads();
    int base = (t >= 32) ? wsum[(t >> 5) - 1] : 0;
    int incl = x + base;
    if (i < N_NODES) g_rowoff[i] = incl - v;   // chunk-local exclusive
    if (t == SCHUNK - 1) g_part[blockIdx.x] = incl;
}
// merged scan2+scan3: each block prefixes the chunk partials in smem
__global__ void scan3_kernel() {
    __shared__ int sp[NCHUNK];
    __shared__ int sbase, stot;
    int t = threadIdx.x;
    if (t < NCHUNK) sp[t] = g_part[t];
    __syncthreads();
    if (t == 0) {
        int c = blockIdx.x >> 2;   // 256*4 = 1024-node chunks
        int b = 0, tot = 0;
        for (int k = 0; k < NCHUNK; k++) { if (k < c) b += sp[k]; tot += sp[k]; }
        sbase = b; stot = tot;
    }
    __syncthreads();
    int i = blockIdx.x * 256 + t;
    if (i < N_NODES) {
        int v = g_rowoff[i] + sbase;
        g_rowoff[i] = v;
        g_cursor[i] = v;
    }
    if (blockIdx.x == 0 && t == 0) g_rowoff[N_NODES] = stot;
}
__global__ void scatter_kernel(const int* __restrict__ ei) {
    int i = blockIdx.x * blockDim.x + threadIdx.x;
    if (i < N_EDGES) {
        int dst = __ldg(&ei[N_EDGES + i]);
        int pos = atomicAdd(&g_cursor[dst], 1);
        g_csr[pos] = __ldg(&ei[i]);
    }
}

// ---------------- node kernel layer 1 ----------------
__global__ void node1_kernel(const float* __restrict__ x, const int* __restrict__ tids,
                             const float* __restrict__ temb, const float* __restrict__ W1,
                             const float* __restrict__ a_s, const float* __restrict__ a_d) {
    __shared__ float Ws[21 * 64];
    __shared__ float xin[4][21];
    __shared__ float redS[8], redD[8];
    int t = threadIdx.x;
    for (int i = t; i < 21 * 64; i += 256) Ws[i] = W1[i];
    int ln = t >> 6, f = t & 63;
    int node = blockIdx.x * 4 + ln;
    if (node < N_NODES && f < 21) {
        if (f < 5) xin[ln][f] = x[node * 5 + f];
        else xin[ln][f] = temb[tids[node] * 16 + (f - 5)];
    }
    __syncthreads();
    int w = t >> 5;
    if (node < N_NODES) {
        float acc = 0.f;
#pragma unroll
        for (int j = 0; j < 21; j++) acc += xin[ln][j] * Ws[j * 64 + f];
        reinterpret_cast<__half*>(g_h16)[node * 64 + f] = __float2half(acc);
        int head = f >> 5, c = f & 31;
        float ps = acc * a_s[head * 32 + c];
        float pd = acc * a_d[head * 32 + c];
#pragma unroll
        for (int o = 16; o; o >>= 1) {
            ps += __shfl_down_sync(0xFFFFFFFFu, ps, o);
            pd += __shfl_down_sync(0xFFFFFFFFu, pd, o);
        }
        if (c == 0) {
            g_als1[node * 2 + head] = ps;
            g_ald1[node * 2 + head] = pd;
            redS[w] = ps; redD[w] = pd;
        }
    } else if ((t & 31) == 0) {
        redS[w] = -1e30f; redD[w] = -1e30f;
    }
    __syncthreads();
    if (t < 4) {
        float* arr = (t < 2) ? redS : redD;
        int h = t & 1;
        float m = fmaxf(fmaxf(arr[h], arr[2 + h]), fmaxf(arr[4 + h], arr[6 + h]));
        atomicMax(&g_maxkey[t], fkey(m));
    }
}

// ---------------- aggregation layer 1: warp per dst, 4 edges // (8 lanes each), index prefetch ----------------
__global__ __launch_bounds__(256) void agg1_kernel(const float* __restrict__ b1) {
    int warp = (blockIdx.x * blockDim.x + threadIdx.x) >> 5;
    int lane = threadIdx.x & 31;
    if (warp >= N_NODES) return;
    int node = warp;
    int quarter = lane >> 3, sub = lane & 7;
    int head = sub >> 2;                    // channels 8*sub..8*sub+7 -> head = sub/4
    float M = leaky(funkey(g_maxkey[head]) + funkey(g_maxkey[2 + head]));
    float ad = __ldg(&g_ald1[node * 2 + head]);
    float a[8] = {0.f, 0.f, 0.f, 0.f, 0.f, 0.f, 0.f, 0.f};
    float denom = 0.f;
    if (quarter == 0) {   // self loop
        float as = __ldg(&g_als1[node * 2 + head]);
        float w = __expf(leaky(as + ad) - M);
        uint4 hv = __ldg(&g_h16[node * 8 + sub]);
        acc8(a, hv, w);
        denom = w;
    }
    int start = g_rowoff[node], end = g_rowoff[node + 1];
    int j0 = start;
    // prefetch first batch of indices
    int i0 = 0, i1 = 0, i2 = 0, i3 = 0;
    if (j0 + 16 <= end) {
        int j = j0 + quarter;
        i0 = __ldg(&g_csr[j]);
        i1 = __ldg(&g_csr[j + 4]);
        i2 = __ldg(&g_csr[j + 8]);
        i3 = __ldg(&g_csr[j + 12]);
    }
    for (; j0 + 16 <= end; j0 += 16) {
        int s0 = i0, s1 = i1, s2 = i2, s3 = i3;
        if (j0 + 32 <= end) {  // prefetch next batch
            int j = j0 + 16 + quarter;
            i0 = __ldg(&g_csr[j]);
            i1 = __ldg(&g_csr[j + 4]);
            i2 = __ldg(&g_csr[j + 8]);
            i3 = __ldg(&g_csr[j + 12]);
        }
        float a0 = __ldg(&g_als1[s0 * 2 + head]);
        float a1 = __ldg(&g_als1[s1 * 2 + head]);
        float a2 = __ldg(&g_als1[s2 * 2 + head]);
        float a3 = __ldg(&g_als1[s3 * 2 + head]);
        uint4 h0 = __ldg(&g_h16[s0 * 8 + sub]);
        uint4 h1 = __ldg(&g_h16[s1 * 8 + sub]);
        uint4 h2 = __ldg(&g_h16[s2 * 8 + sub]);
        uint4 h3 = __ldg(&g_h16[s3 * 8 + sub]);
        float w0 = __expf(leaky(a0 + ad) - M);
        float w1 = __expf(leaky(a1 + ad) - M);
        float w2 = __expf(leaky(a2 + ad) - M);
        float w3 = __expf(leaky(a3 + ad) - M);
        acc8(a, h0, w0); acc8(a, h1, w1); acc8(a, h2, w2); acc8(a, h3, w3);
        denom += w0 + w1 + w2 + w3;
    }
    // remainder: < 16 edges -> single predicated batch (w=0 masks invalid)
    if (j0 < end) {
        int j = j0 + quarter;
        bool p0 = j < end, p1 = j + 4 < end, p2 = j + 8 < end, p3 = j + 12 < end;
        int s0 = p0 ? __ldg(&g_csr[j]) : 0;
        int s1 = p1 ? __ldg(&g_csr[j + 4]) : 0;
        int s2 = p2 ? __ldg(&g_csr[j + 8]) : 0;
        int s3 = p3 ? __ldg(&g_csr[j + 12]) : 0;
        float a0 = __ldg(&g_als1[s0 * 2 + head]);
        float a1 = __ldg(&g_als1[s1 * 2 + head]);
        float a2 = __ldg(&g_als1[s2 * 2 + head]);
        float a3 = __ldg(&g_als1[s3 * 2 + head]);
        uint4 h0 = __ldg(&g_h16[s0 * 8 + sub]);
        uint4 h1 = __ldg(&g_h16[s1 * 8 + sub]);
        uint4 h2 = __ldg(&g_h16[s2 * 8 + sub]);
        uint4 h3 = __ldg(&g_h16[s3 * 8 + sub]);
        float w0 = p0 ? __expf(leaky(a0 + ad) - M) : 0.f;
        float w1 = p1 ? __expf(leaky(a1 + ad) - M) : 0.f;
        float w2 = p2 ? __expf(leaky(a2 + ad) - M) : 0.f;
        float w3 = p3 ? __expf(leaky(a3 + ad) - M) : 0.f;
        acc8(a, h0, w0); acc8(a, h1, w1); acc8(a, h2, w2); acc8(a, h3, w3);
        denom += w0 + w1 + w2 + w3;
    }
    // combine quarters (lane bits 3 and 4)
#pragma unroll
    for (int i = 0; i < 8; i++) {
        a[i] += __shfl_xor_sync(0xFFFFFFFFu, a[i], 8);
        a[i] += __shfl_xor_sync(0xFFFFFFFFu, a[i], 16);
    }
    denom += __shfl_xor_sync(0xFFFFFFFFu, denom, 8);
    denom += __shfl_xor_sync(0xFFFFFFFFu, denom, 16);
    if (quarter == 0) {
        float inv = 1.f / (denom + 1e-16f);
        float4 b0 = *(const float4*)&b1[8 * sub];
        float4 b4 = *(const float4*)&b1[8 * sub + 4];
        float4 o0, o1;
        o0.x = fmaxf(a[0] * inv + b0.x, 0.f);
        o0.y = fmaxf(a[1] * inv + b0.y, 0.f);
        o0.z = fmaxf(a[2] * inv + b0.z, 0.f);
        o0.w = fmaxf(a[3] * inv + b0.w, 0.f);
        o1.x = fmaxf(a[4] * inv + b4.x, 0.f);
        o1.y = fmaxf(a[5] * inv + b4.y, 0.f);
        o1.z = fmaxf(a[6] * inv + b4.z, 0.f);
        o1.w = fmaxf(a[7] * inv + b4.w, 0.f);
        *(float4*)&g_act[node * 64 + 8 * sub] = o0;
        *(float4*)&g_act[node * 64 + 8 * sub + 4] = o1;
    }
}

// ---------------- node kernel layer 2 ----------------
__global__ void node2_kernel(const float* __restrict__ W2, const float* __restrict__ a_s2,
                             const float* __restrict__ a_d2) {
    __shared__ float Ws[64 * 64];
    __shared__ float xin[4][64];
    __shared__ float redS[8], redD[8];
    __shared__ float asv[4], adv[4];
    int t = threadIdx.x;
    for (int i = t; i < 64 * 64; i += 256) Ws[i] = W2[i];
    int ln = t >> 6, f = t & 63;
    int node = blockIdx.x * 4 + ln;
    if (node < N_NODES) xin[ln][f] = g_act[node * 64 + f];
    __syncthreads();
    float ps = 0.f, pd = 0.f;
    if (node < N_NODES) {
        float acc = 0.f;
#pragma unroll
        for (int j = 0; j < 64; j++) acc += xin[ln][j] * Ws[j * 64 + f];
        reinterpret_cast<__half*>(g_h16)[node * 64 + f] = __float2half(acc);
        ps = acc * a_s2[f];
        pd = acc * a_d2[f];
    }
#pragma unroll
    for (int o = 16; o; o >>= 1) {
        ps += __shfl_down_sync(0xFFFFFFFFu, ps, o);
        pd += __shfl_down_sync(0xFFFFFFFFu, pd, o);
    }
    int w = t >> 5;
    if ((t & 31) == 0) { redS[w] = ps; redD[w] = pd; }
    __syncthreads();
    if (t < 4) {
        int nd = blockIdx.x * 4 + t;
        if (nd < N_NODES) {
            float as = redS[2 * t] + redS[2 * t + 1];
            float ad = redD[2 * t] + redD[2 * t + 1];
            g_als2[nd] = as; g_ald2[nd] = ad;
            asv[t] = as; adv[t] = ad;
        } else { asv[t] = -1e30f; adv[t] = -1e30f; }
    }
    __syncthreads();
    if (t == 0) {
        float ms = fmaxf(fmaxf(asv[0], asv[1]), fmaxf(asv[2], asv[3]));
        float md = fmaxf(fmaxf(adv[0], adv[1]), fmaxf(adv[2], adv[3]));
        atomicMax(&g_maxkey[4], fkey(ms));
        atomicMax(&g_maxkey[5], fkey(md));
    }
}

// ---------------- aggregation layer 2: warp per dst, prefetch, fused LayerNorm ----------------
__global__ __launch_bounds__(256) void agg2_kernel(const float* __restrict__ b2,
                                                   const float* __restrict__ gamma,
                                                   const float* __restrict__ beta,
                                                   float* __restrict__ out) {
    int warp = (blockIdx.x * blockDim.x + threadIdx.x) >> 5;
    int lane = threadIdx.x & 31;
    if (warp >= N_NODES) return;
    int node = warp;
    int quarter = lane >> 3, sub = lane & 7;
    float M = leaky(funkey(g_maxkey[4]) + funkey(g_maxkey[5]));
    float ad = __ldg(&g_ald2[node]);
    float a[8] = {0.f, 0.f, 0.f, 0.f, 0.f, 0.f, 0.f, 0.f};
    float denom = 0.f;
    if (quarter == 0) {
        float w = __expf(leaky(__ldg(&g_als2[node]) + ad) - M);
        uint4 hv = __ldg(&g_h16[node * 8 + sub]);
        acc8(a, hv, w);
        denom = w;
    }
    int start = g_rowoff[node], end = g_rowoff[node + 1];
    int j0 = start;
    int i0 = 0, i1 = 0, i2 = 0, i3 = 0;
    if (j0 + 16 <= end) {
        int j = j0 + quarter;
        i0 = __ldg(&g_csr[j]);
        i1 = __ldg(&g_csr[j + 4]);
        i2 = __ldg(&g_csr[j + 8]);
        i3 = __ldg(&g_csr[j + 12]);
    }
    for (; j0 + 16 <= end; j0 += 16) {
        int s0 = i0, s1 = i1, s2 = i2, s3 = i3;
        if (j0 + 32 <= end) {
            int j = j0 + 16 + quarter;
            i0 = __ldg(&g_csr[j]);
            i1 = __ldg(&g_csr[j + 4]);
            i2 = __ldg(&g_csr[j + 8]);
            i3 = __ldg(&g_csr[j + 12]);
        }
        float a0 = __ldg(&g_als2[s0]);
        float a1 = __ldg(&g_als2[s1]);
        float a2 = __ldg(&g_als2[s2]);
        float a3 = __ldg(&g_als2[s3]);
        uint4 h0 = __ldg(&g_h16[s0 * 8 + sub]);
        uint4 h1 = __ldg(&g_h16[s1 * 8 + sub]);
        uint4 h2 = __ldg(&g_h16[s2 * 8 + sub]);
        uint4 h3 = __ldg(&g_h16[s3 * 8 + sub]);
        float w0 = __expf(leaky(a0 + ad) - M);
        float w1 = __expf(leaky(a1 + ad) - M);
        float w2 = __expf(leaky(a2 + ad) - M);
        float w3 = __expf(leaky(a3 + ad) - M);
        acc8(a, h0, w0); acc8(a, h1, w1); acc8(a, h2, w2); acc8(a, h3, w3);
        denom += w0 + w1 + w2 + w3;
    }
    if (j0 < end) {
        int j = j0 + quarter;
        bool p0 = j < end, p1 = j + 4 < end, p2 = j + 8 < end, p3 = j + 12 < end;
        int s0 = p0 ? __ldg(&g_csr[j]) : 0;
        int s1 = p1 ? __ldg(&g_csr[j + 4]) : 0;
        int s2 = p2 ? __ldg(&g_csr[j + 8]) : 0;
        int s3 = p3 ? __ldg(&g_csr[j + 12]) : 0;
        float a0 = __ldg(&g_als2[s0]);
        float a1 = __ldg(&g_als2[s1]);
        float a2 = __ldg(&g_als2[s2]);
        float a3 = __ldg(&g_als2[s3]);
        uint4 h0 = __ldg(&g_h16[s0 * 8 + sub]);
        uint4 h1 = __ldg(&g_h16[s1 * 8 + sub]);
        uint4 h2 = __ldg(&g_h16[s2 * 8 + sub]);
        uint4 h3 = __ldg(&g_h16[s3 * 8 + sub]);
        float w0 = p0 ? __expf(leaky(a0 + ad) - M) : 0.f;
        float w1 = p1 ? __expf(leaky(a1 + ad) - M) : 0.f;
        float w2 = p2 ? __expf(leaky(a2 + ad) - M) : 0.f;
        float w3 = p3 ? __expf(leaky(a3 + ad) - M) : 0.f;
        acc8(a, h0, w0); acc8(a, h1, w1); acc8(a, h2, w2); acc8(a, h3, w3);
        denom += w0 + w1 + w2 + w3;
    }
#pragma unroll
    for (int i = 0; i < 8; i++) {
        a[i] += __shfl_xor_sync(0xFFFFFFFFu, a[i], 8);
        a[i] += __shfl_xor_sync(0xFFFFFFFFu, a[i], 16);
    }
    denom += __shfl_xor_sync(0xFFFFFFFFu, denom, 8);
    denom += __shfl_xor_sync(0xFFFFFFFFu, denom, 16);
    float inv = 1.f / (denom + 1e-16f);
    float4 b0 = *(const float4*)&b2[8 * sub];
    float4 b4 = *(const float4*)&b2[8 * sub + 4];
    float v[8];
    v[0] = a[0] * inv + b0.x; v[1] = a[1] * inv + b0.y;
    v[2] = a[2] * inv + b0.z; v[3] = a[3] * inv + b0.w;
    v[4] = a[4] * inv + b4.x; v[5] = a[5] * inv + b4.y;
    v[6] = a[6] * inv + b4.z; v[7] = a[7] * inv + b4.w;
    // LayerNorm over 64 channels (8/lane across 8 sub-lanes; quarters identical)
    float s = 0.f, q = 0.f;
#pragma unroll
    for (int i = 0; i < 8; i++) { s += v[i]; q += v[i] * v[i]; }
#pragma unroll
    for (int o = 4; o; o >>= 1) {
        s += __shfl_xor_sync(0xFFFFFFFFu, s, o);
        q += __shfl_xor_sync(0xFFFFFFFFu, q, o);
    }
    if (quarter == 0) {
        float mu = s * (1.f / 64.f);
        float var = q * (1.f / 64.f) - mu * mu;
        float rinv = rsqrtf(var + 1e-5f);
        float4 g0 = *(const float4*)&gamma[8 * sub];
        float4 g4 = *(const float4*)&gamma[8 * sub + 4];
        float4 e0 = *(const float4*)&beta[8 * sub];
        float4 e4 = *(const float4*)&beta[8 * sub + 4];
        float4 o0, o1;
        o0.x = (v[0] - mu) * rinv * g0.x + e0.x;
        o0.y = (v[1] - mu) * rinv * g0.y + e0.y;
        o0.z = (v[2] - mu) * rinv * g0.z + e0.z;
        o0.w = (v[3] - mu) * rinv * g0.w + e0.w;
        o1.x = (v[4] - mu) * rinv * g4.x + e4.x;
        o1.y = (v[5] - mu) * rinv * g4.y + e4.y;
        o1.z = (v[6] - mu) * rinv * g4.z + e4.z;
        o1.w = (v[7] - mu) * rinv * g4.w + e4.w;
        *(float4*)&out[node * 64 + 8 * sub] = o0;
        *(float4*)&out[node * 64 + 8 * sub + 4] = o1;
    }
}

// ---------------- launch ----------------
extern "C" void kernel_launch(void* const* d_in, const int* in_sizes, int n_in,
                              void* d_out, int out_size) {
    const float *x, *temb, *W1, *as1, *ad1, *b1, *W2, *as2, *ad2, *b2, *gamma, *beta;
    const int *ei, *tids;
    if (in_sizes[1] == 2 * N_EDGES) {
        x    = (const float*)d_in[0];
        ei   = (const int*)d_in[1];
        tids = (const int*)d_in[2];
        temb = (const float*)d_in[3];
        W1   = (const float*)d_in[4];
        as1  = (const float*)d_in[5];
        ad1  = (const float*)d_in[6];
        b1   = (const float*)d_in[7];
        W2   = (const float*)d_in[8];
        as2  = (const float*)d_in[9];
        ad2  = (const float*)d_in[10];
        b2   = (const float*)d_in[11];
        gamma= (const float*)d_in[12];
        beta = (const float*)d_in[13];
    } else {
        x    = (const float*)d_in[0];
        temb = (const float*)d_in[1];
        W1   = (const float*)d_in[2];
        as1  = (const float*)d_in[3];
        ad1  = (const float*)d_in[4];
        b1   = (const float*)d_in[5];
        W2   = (const float*)d_in[6];
        as2  = (const float*)d_in[7];
        ad2  = (const float*)d_in[8];
        b2   = (const float*)d_in[9];
        gamma= (const float*)d_in[10];
        beta = (const float*)d_in[11];
        ei   = (const int*)d_in[12];
        tids = (const int*)d_in[13];
    }
    float* out = (float*)d_out;

    const int nodeB  = (N_NODES + 255) / 256;
    const int edgeB  = (N_EDGES + 255) / 256;
    const int gemvB  = (N_NODES + 3) / 4;
    const int aggB   = (N_NODES * 32 + 255) / 256;

    zero_kernel<<<nodeB, 256>>>();
    hist_kernel<<<edgeB, 256>>>(ei);
    scan1_kernel<<<NCHUNK, SCHUNK>>>();
    scan3_kernel<<<nodeB, 256>>>();
    scatter_kernel<<<edgeB, 256>>>(ei);
    node1_kernel<<<gemvB, 256>>>(x, tids, temb, W1, as1, ad1);
    agg1_kernel<<<aggB, 256>>>(b1);
    node2_kernel<<<gemvB, 256>>>(W2, as2, ad2);
    agg2_kernel<<<aggB, 256>>>(b2, gamma, beta, out);
}